// round 11
// baseline (speedup 1.0000x reference)
#include <cuda_runtime.h>

#define LSZ   4096
#define BATCH 64
#define R1    48
#define R2    16
#define NIN   1024
#define FCN   512
#define NCLS  10

// ---------------- scratch (device globals; no allocation allowed) ----------------
__device__ float g_da1[LSZ], g_db1[LSZ], g_da2[LSZ], g_db2[LSZ];
__device__ float g_ida1[LSZ], g_idb1[LSZ], g_ida2[LSZ], g_idb2[LSZ];
__device__ float g_Gt1[R1*LSZ], g_Ht1[R1*LSZ];
__device__ float g_Gt2[R2*LSZ], g_Ht2[R2*LSZ];
__device__ float g_M[(size_t)LSZ*1024];     // 16MB Q strip; layer2 uses 512*4096 = 8MB
__device__ float g_sub[256*256];            // per-subtile diagonal totals (max 32*8 subtiles)
__device__ float g_z1[BATCH*NIN];           // layer-1 input, compact 64x1024
__device__ float g_z2[BATCH*LSZ];           // layer-2 input, 64x4096
__device__ float g_Ypart[8*BATCH*LSZ];      // split-K partials: L1 8 slices, L2 32 slices of 64x512

// ---------------- cumprod scan: d[0]=1, d[j]=prod_{k<j} subd[k]; also reciprocals ------------
__global__ void scan_kernel(const float* __restrict__ sA1, const float* __restrict__ sB1,
                            const float* __restrict__ sA2, const float* __restrict__ sB2) {
    const float* src; float* dst; float* inv;
    if      (blockIdx.x == 0) { src = sA1; dst = g_da1; inv = g_ida1; }
    else if (blockIdx.x == 1) { src = sB1; dst = g_db1; inv = g_idb1; }
    else if (blockIdx.x == 2) { src = sA2; dst = g_da2; inv = g_ida2; }
    else                      { src = sB2; dst = g_db2; inv = g_idb2; }

    __shared__ float part[1024];
    int tid = threadIdx.x;
    float v[4]; float p = 1.f;
#pragma unroll
    for (int j = 0; j < 4; j++) {
        int idx = tid * 4 + j;
        float s = (idx < LSZ - 1) ? src[idx] : 1.f;
        p *= s; v[j] = p;
    }
    part[tid] = p; __syncthreads();
    for (int off = 1; off < 1024; off <<= 1) {
        float x = part[tid];
        float m = (tid >= off) ? part[tid - off] : 1.f;
        __syncthreads();
        part[tid] = x * m;
        __syncthreads();
    }
    float excl = (tid == 0) ? 1.f : part[tid - 1];
    if (tid == 0) { dst[0] = 1.f; inv[0] = 1.f; }
#pragma unroll
    for (int j = 0; j < 4; j++) {
        int idx = tid * 4 + j;
        if (idx < LSZ - 1) {
            float val = excl * v[j];
            dst[idx + 1] = val;
            inv[idx + 1] = 1.0f / val;
        }
    }
}

// ---------------- prep: Gt=G*ida, Ht=H*idb, z1 = db1 * x (compact 1024) ----------------
__global__ void prep_kernel(const float* __restrict__ G1, const float* __restrict__ H1,
                            const float* __restrict__ G2, const float* __restrict__ H2,
                            const float* __restrict__ x) {
    int tid = blockIdx.x * blockDim.x + threadIdx.x;
    int j = tid & (LSZ - 1);
    if (tid < R1 * LSZ) {
        g_Gt1[tid] = G1[tid] * g_ida1[j];
        g_Ht1[tid] = H1[tid] * g_idb1[j];
    }
    if (tid < R2 * LSZ) {
        g_Gt2[tid] = G2[tid] * g_ida2[j];
        g_Ht2[tid] = H2[tid] * g_idb2[j];
    }
    if (tid < BATCH * NIN) {
        int jj = tid & (NIN - 1);
        g_z1[tid] = x[tid] * g_db1[jj];
    }
}

// ---------------- Q = Gt^T Ht + per-subtile diagonal totals ----------------
// Q[t][w]; 128x128 tile; k = blockIdx.y (t-tile), c = blockIdx.x (w-chunk), NC = ld/128.
// After mainloop, accumulators are parked in smem and 255 threads sum each local diagonal.
template <int R>
__global__ __launch_bounds__(256, 2) void qgemm_kernel(const float* __restrict__ Gt,
                                                       const float* __restrict__ Ht,
                                                       float* __restrict__ Q, int ld,
                                                       float* __restrict__ sub) {
    extern __shared__ float sh[];
    float* sG = sh;             // R x 132
    float* sH = sh + R * 132;   // R x 132   (tile reuses sh after mainloop)
    int k = blockIdx.y, c = blockIdx.x;
    int NC = ld >> 7;
    int t0 = k << 7, w0 = c << 7;
    for (int idx = threadIdx.x; idx < R * 128; idx += 256) {
        int i = idx >> 7, e = idx & 127;
        sG[i * 132 + e] = Gt[i * LSZ + t0 + e];
        sH[i * 132 + e] = Ht[i * LSZ + w0 + e];
    }
    __syncthreads();

    int tx = threadIdx.x & 15, ty = threadIdx.x >> 4;
    float acc[8][8];
#pragma unroll
    for (int u = 0; u < 8; u++)
#pragma unroll
        for (int v = 0; v < 8; v++) acc[u][v] = 0.f;

    for (int i = 0; i < R; i++) {
        float a[8], b[8];
        ((float4*)a)[0] = *(const float4*)&sG[i * 132 + ty * 4];
        ((float4*)a)[1] = *(const float4*)&sG[i * 132 + 64 + ty * 4];
        ((float4*)b)[0] = *(const float4*)&sH[i * 132 + tx * 4];
        ((float4*)b)[1] = *(const float4*)&sH[i * 132 + 64 + tx * 4];
#pragma unroll
        for (int u = 0; u < 8; u++)
#pragma unroll
            for (int v = 0; v < 8; v++) acc[u][v] = fmaf(a[u], b[v], acc[u][v]);
    }
    // global stores
#pragma unroll
    for (int u = 0; u < 8; u++) {
        int t = t0 + (u < 4 ? ty * 4 + u : 64 + ty * 4 + u - 4);
        *(float4*)&Q[(size_t)t * ld + w0 + tx * 4]      = make_float4(acc[u][0], acc[u][1], acc[u][2], acc[u][3]);
        *(float4*)&Q[(size_t)t * ld + w0 + 64 + tx * 4] = make_float4(acc[u][4], acc[u][5], acc[u][6], acc[u][7]);
    }
    __syncthreads();   // everyone done reading sG/sH
    // park tile in smem (reuse sh): 128 x 132
    float* sT = sh;
#pragma unroll
    for (int u = 0; u < 8; u++) {
        int row = (u < 4 ? ty * 4 + u : 64 + ty * 4 + u - 4);
        *(float4*)&sT[row * 132 + tx * 4]      = make_float4(acc[u][0], acc[u][1], acc[u][2], acc[u][3]);
        *(float4*)&sT[row * 132 + 64 + tx * 4] = make_float4(acc[u][4], acc[u][5], acc[u][6], acc[u][7]);
    }
    __syncthreads();
    // per-diagonal totals: local diag dl = tid-127; clamped pointer walk (stride 133)
    int tid = threadIdx.x;
    if (tid < 255) {
        int dl = tid - 127;
        int rlo = dl > 0 ? dl : 0;
        int rhi = dl > 0 ? 128 : 128 + dl;
        const float* p = &sT[rlo * 133 - dl];
        float s = 0.f;
#pragma unroll 4
        for (int r = rlo; r < rhi; r++) {
            s += *p;
            p += 133;
        }
        sub[(k * NC + c) * 256 + tid] = s;
    } else {
        sub[(k * NC + c) * 256 + 255] = 0.f;
    }
}

// ---------------- main GEMM with fused prefix + in-smem diagonal cumsum ----------------
// Ypart[c][b][t] = sum_{w in chunk c} M[t][w] z[b][w], M = diag-cumsum(Q).
// One 128-wide chunk per CTA (blockIdx.y = c); blockIdx.z = batch slice of NB rows.
// Loads raw Q tile; while loads are in flight, computes the diagonal entering prefix from
// g_sub; cumsums in smem (register-chunked to break the serial LDS chain); float4 FMA loop.
template <int NB>
__global__ __launch_bounds__(256, 2) void skewgemm_kernel(const float* __restrict__ Q, int ld,
                                                          const float* __restrict__ z, int zld,
                                                          const float* __restrict__ sub,
                                                          float* __restrict__ Ypart, int Tdim) {
    extern __shared__ float sh[];
    float* sM = sh;                 // 128 x 132
    float* sz = sh + 128 * 132;     // NB x 132
    int k = blockIdx.x;
    int c = blockIdx.y;
    int b0 = blockIdx.z * NB;
    int t0 = k << 7;
    int w0 = c << 7;
    int NC = ld >> 7;
    int tx = threadIdx.x & 15, ty = threadIdx.x >> 4;
    int tid = threadIdx.x;
    const int NV = NB / 16;
    float acc[8][NV];
#pragma unroll
    for (int u = 0; u < 8; u++)
#pragma unroll
        for (int v = 0; v < NV; v++) acc[u][v] = 0.f;

    for (int idx = tid; idx < 128 * 32; idx += 256) {
        int row = idx >> 5, c4 = idx & 31;
        float4 m4 = *(const float4*)&Q[(size_t)(t0 + row) * ld + w0 + 4 * c4];
        *(float4*)&sM[row * 132 + 4 * c4] = m4;
    }
    for (int idx = tid; idx < NB * 32; idx += 256) {
        int b = idx >> 5, c4 = idx & 31;
        float4 z4 = *(const float4*)&z[(size_t)(b0 + b) * zld + w0 + 4 * c4];
        *(float4*)&sz[b * 132 + 4 * c4] = z4;
    }
    // ---- prefix for (k,c), overlapped with the tile loads above ----
    // global diag d = 128*(k-c) + (tid-127); earlier subtiles: k2<k any chunk, or k2==k c2<c.
    // chunk candidates per t-tile: q = k2-c2 in {d>>7, (d+127)>>7}.
    float pacc = 0.f;
    if (tid < 255) {
        int d = ((k - c) << 7) + (tid - 127);
        int qlo = d >> 7;
        int qhi = (d + 127) >> 7;
        int jlo = (d - (qlo << 7)) + 127;
        int jhi = (d - (qhi << 7)) + 127;
        for (int k2 = 0; k2 < k; k2++) {
            int c2 = k2 - qlo;
            if (c2 >= 0 && c2 < NC) pacc += sub[(k2 * NC + c2) * 256 + jlo];
            if (qhi != qlo) {
                c2 = k2 - qhi;
                if (c2 >= 0 && c2 < NC) pacc += sub[(k2 * NC + c2) * 256 + jhi];
            }
        }
        int c2 = k - qlo;
        if (c2 >= 0 && c2 < c) pacc += sub[(k * NC + c2) * 256 + jlo];
        if (qhi != qlo) {
            c2 = k - qhi;
            if (c2 >= 0 && c2 < c) pacc += sub[(k * NC + c2) * 256 + jhi];
        }
    }
    __syncthreads();
    // in-smem segmented diagonal cumsum on sM, seeded by pacc.
    // Diagonal = pointer walk with stride 133; chunks of 16 loaded into registers first
    // (independent LDS, pipelined), then serial FADD + store.
    if (tid < 255) {
        int dl = tid - 127;
        int rlo = dl > 0 ? dl : 0;
        int rhi = dl > 0 ? 128 : 128 + dl;
        int len = rhi - rlo;
        float* p = &sM[rlo * 133 - dl];
        float a = pacc;
        int r = 0;
        for (; r + 16 <= len; r += 16) {
            float v[16];
#pragma unroll
            for (int j = 0; j < 16; j++) v[j] = p[j * 133];
#pragma unroll
            for (int j = 0; j < 16; j++) { a += v[j]; p[j * 133] = a; }
            p += 16 * 133;
        }
        for (; r < len; r++) { a += *p; *p = a; p += 133; }
    }
    __syncthreads();
    // ---- FMA mainloop, float4 along ww ----
#pragma unroll 2
    for (int ww = 0; ww < 128; ww += 4) {
        float4 a4[8], z4[NV];
#pragma unroll
        for (int u = 0; u < 8; u++) a4[u] = *(const float4*)&sM[(tx + 16 * u) * 132 + ww];
#pragma unroll
        for (int v = 0; v < NV; v++) z4[v] = *(const float4*)&sz[(ty + 16 * v) * 132 + ww];
#pragma unroll
        for (int u = 0; u < 8; u++)
#pragma unroll
            for (int v = 0; v < NV; v++) {
                acc[u][v] = fmaf(a4[u].x, z4[v].x, acc[u][v]);
                acc[u][v] = fmaf(a4[u].y, z4[v].y, acc[u][v]);
                acc[u][v] = fmaf(a4[u].z, z4[v].z, acc[u][v]);
                acc[u][v] = fmaf(a4[u].w, z4[v].w, acc[u][v]);
            }
    }
#pragma unroll
    for (int u = 0; u < 8; u++) {
        int t = t0 + tx + 16 * u;
#pragma unroll
        for (int v = 0; v < NV; v++) {
            int b = b0 + ty + 16 * v;
            Ypart[((size_t)c * BATCH + b) * Tdim + t] = acc[u][v];
        }
    }
}

// ---------------- epilogue 1: reduce 8 partials, z2 = relu(da1*s + b1) * db2 (full 4096) -------
__global__ void epilogue1_kernel(const float* __restrict__ bias) {
    int i4 = blockIdx.x * 256 + threadIdx.x;
    if (i4 >= BATCH * LSZ / 4) return;
    const float4* Yp = (const float4*)g_Ypart;
    float4 s = Yp[i4];
#pragma unroll
    for (int k = 1; k < 8; k++) {
        float4 p = Yp[(size_t)k * (BATCH * LSZ / 4) + i4];
        s.x += p.x; s.y += p.y; s.z += p.z; s.w += p.w;
    }
    int t = (i4 * 4) & (LSZ - 1);
    float4 dav = *(const float4*)&g_da1[t];
    float4 bv  = *(const float4*)&bias[t];
    float4 db  = *(const float4*)&g_db2[t];
    float4 h;
    h.x = fmaxf(dav.x * s.x + bv.x, 0.f) * db.x;
    h.y = fmaxf(dav.y * s.y + bv.y, 0.f) * db.y;
    h.z = fmaxf(dav.z * s.z + bv.z, 0.f) * db.z;
    h.w = fmaxf(dav.w * s.w + bv.w, 0.f) * db.w;
    ((float4*)g_z2)[i4] = h;
}

// ---------------- fused epilogue2 + logits ----------------
__global__ __launch_bounds__(512) void epilogits_kernel(const float* __restrict__ bias,
                                                        const float* __restrict__ W,
                                                        const float* __restrict__ bl,
                                                        float* __restrict__ out) {
    __shared__ float sh2[FCN];
    int b = blockIdx.x;
    int t = threadIdx.x;            // 512 threads = one t each
    float s = 0.f;
#pragma unroll
    for (int k = 0; k < 32; k++) s += g_Ypart[(size_t)k * BATCH * FCN + b * FCN + t];
    sh2[t] = fmaxf(g_da2[t] * s + bias[t], 0.f);
    __syncthreads();
    int cls = t >> 5;
    int lane = t & 31;
    if (cls < NCLS) {
        float acc = 0.f;
#pragma unroll
        for (int m = 0; m < 16; m++) {
            int j = lane + 32 * m;
            acc = fmaf(sh2[j], W[cls * FCN + j], acc);
        }
#pragma unroll
        for (int off = 16; off; off >>= 1) acc += __shfl_down_sync(0xffffffffu, acc, off);
        if (lane == 0) out[b * NCLS + cls] = acc + bl[cls];
    }
}

// ---------------- launch ----------------
extern "C" void kernel_launch(void* const* d_in, const int* in_sizes, int n_in,
                              void* d_out, int out_size) {
    const float* x    = (const float*)d_in[0];
    const float* G1   = (const float*)d_in[1];
    const float* H1   = (const float*)d_in[2];
    const float* sdA1 = (const float*)d_in[3];
    const float* sdB1 = (const float*)d_in[4];
    const float* b1   = (const float*)d_in[5];
    const float* G2   = (const float*)d_in[6];
    const float* H2   = (const float*)d_in[7];
    const float* sdA2 = (const float*)d_in[8];
    const float* sdB2 = (const float*)d_in[9];
    const float* b2   = (const float*)d_in[10];
    const float* W    = (const float*)d_in[11];
    const float* bl   = (const float*)d_in[12];
    float* out = (float*)d_out;

    const int QSM  = 128 * 132 * 4;               // 67584 (tile park; >= 2*R*132*4 for R<=48)
    const int GSM1 = (128 * 132 + 64 * 132) * 4;  // 101376 (NB=64)
    const int GSM2 = (128 * 132 + 32 * 132) * 4;  // 84480  (NB=32)

    cudaFuncSetAttribute(qgemm_kernel<R1>, cudaFuncAttributeMaxDynamicSharedMemorySize, QSM);
    cudaFuncSetAttribute(qgemm_kernel<R2>, cudaFuncAttributeMaxDynamicSharedMemorySize, QSM);
    cudaFuncSetAttribute(skewgemm_kernel<64>, cudaFuncAttributeMaxDynamicSharedMemorySize, GSM1);
    cudaFuncSetAttribute(skewgemm_kernel<32>, cudaFuncAttributeMaxDynamicSharedMemorySize, GSM2);

    float* Mbuf;  cudaGetSymbolAddress((void**)&Mbuf, g_M);
    float* Sub;   cudaGetSymbolAddress((void**)&Sub, g_sub);
    float* Ypart; cudaGetSymbolAddress((void**)&Ypart, g_Ypart);
    float* z1;    cudaGetSymbolAddress((void**)&z1, g_z1);
    float* z2;    cudaGetSymbolAddress((void**)&z2, g_z2);
    float* Gt1;   cudaGetSymbolAddress((void**)&Gt1, g_Gt1);
    float* Ht1;   cudaGetSymbolAddress((void**)&Ht1, g_Ht1);
    float* Gt2;   cudaGetSymbolAddress((void**)&Gt2, g_Gt2);
    float* Ht2;   cudaGetSymbolAddress((void**)&Ht2, g_Ht2);

    scan_kernel<<<4, 1024>>>(sdA1, sdB1, sdA2, sdB2);
    prep_kernel<<<1024, 256>>>(G1, H1, G2, H2, x);

    // ---- layer 1: strip 4096 x 1024 (input zero-padded beyond 1024); NC=8 ----
    qgemm_kernel<R1><<<dim3(8, 32), 256, QSM>>>(Gt1, Ht1, Mbuf, 1024, Sub);
    skewgemm_kernel<64><<<dim3(32, 8, 1), 256, GSM1>>>(Mbuf, 1024, z1, 1024, Sub, Ypart, LSZ);
    epilogue1_kernel<<<256, 256>>>(b1);

    // ---- layer 2: strip 512 x 4096 (only first 512 outputs used); NC=32 ----
    qgemm_kernel<R2><<<dim3(32, 4), 256, QSM>>>(Gt2, Ht2, Mbuf, 4096, Sub);
    skewgemm_kernel<32><<<dim3(4, 32, 2), 256, GSM2>>>(Mbuf, 4096, z2, 4096, Sub, Ypart, FCN);
    epilogits_kernel<<<64, 512>>>(b2, W, bl, out);
}

// round 12
// speedup vs baseline: 1.0033x; 1.0033x over previous
#include <cuda_runtime.h>

#define LSZ   4096
#define BATCH 64
#define R1    48
#define R2    16
#define NIN   1024
#define FCN   512
#define NCLS  10

// ---------------- scratch (device globals; no allocation allowed) ----------------
__device__ float g_da1[LSZ], g_db1[LSZ], g_da2[LSZ], g_db2[LSZ];
__device__ float g_ida1[LSZ], g_idb1[LSZ], g_ida2[LSZ], g_idb2[LSZ];
__device__ float g_Gt1[R1*LSZ], g_Ht1[R1*LSZ];
__device__ float g_Gt2[R2*LSZ], g_Ht2[R2*LSZ];
__device__ float g_M[(size_t)LSZ*1024];     // 16MB Q strip; layer2 uses 512*4096 = 8MB
__device__ float g_sub[256*256];            // per-subtile diagonal totals (max 32*8 subtiles)
__device__ float g_z1[BATCH*NIN];           // layer-1 input, compact 64x1024
__device__ float g_z2[BATCH*LSZ];           // layer-2 input, 64x4096
__device__ float g_Ypart[8*BATCH*LSZ];      // split-K partials: L1 8 slices, L2 32 slices of 64x512

// ---------------- cumprod scan: d[0]=1, d[j]=prod_{k<j} subd[k]; also reciprocals ------------
__global__ void scan_kernel(const float* __restrict__ sA1, const float* __restrict__ sB1,
                            const float* __restrict__ sA2, const float* __restrict__ sB2) {
    const float* src; float* dst; float* inv;
    if      (blockIdx.x == 0) { src = sA1; dst = g_da1; inv = g_ida1; }
    else if (blockIdx.x == 1) { src = sB1; dst = g_db1; inv = g_idb1; }
    else if (blockIdx.x == 2) { src = sA2; dst = g_da2; inv = g_ida2; }
    else                      { src = sB2; dst = g_db2; inv = g_idb2; }

    __shared__ float part[1024];
    int tid = threadIdx.x;
    float v[4]; float p = 1.f;
#pragma unroll
    for (int j = 0; j < 4; j++) {
        int idx = tid * 4 + j;
        float s = (idx < LSZ - 1) ? src[idx] : 1.f;
        p *= s; v[j] = p;
    }
    part[tid] = p; __syncthreads();
    for (int off = 1; off < 1024; off <<= 1) {
        float x = part[tid];
        float m = (tid >= off) ? part[tid - off] : 1.f;
        __syncthreads();
        part[tid] = x * m;
        __syncthreads();
    }
    float excl = (tid == 0) ? 1.f : part[tid - 1];
    if (tid == 0) { dst[0] = 1.f; inv[0] = 1.f; }
#pragma unroll
    for (int j = 0; j < 4; j++) {
        int idx = tid * 4 + j;
        if (idx < LSZ - 1) {
            float val = excl * v[j];
            dst[idx + 1] = val;
            inv[idx + 1] = 1.0f / val;
        }
    }
}

// ---------------- prep: Gt=G*ida, Ht=H*idb, z1 = db1 * x (compact 1024) ----------------
__global__ void prep_kernel(const float* __restrict__ G1, const float* __restrict__ H1,
                            const float* __restrict__ G2, const float* __restrict__ H2,
                            const float* __restrict__ x) {
    int tid = blockIdx.x * blockDim.x + threadIdx.x;
    int j = tid & (LSZ - 1);
    if (tid < R1 * LSZ) {
        g_Gt1[tid] = G1[tid] * g_ida1[j];
        g_Ht1[tid] = H1[tid] * g_idb1[j];
    }
    if (tid < R2 * LSZ) {
        g_Gt2[tid] = G2[tid] * g_ida2[j];
        g_Ht2[tid] = H2[tid] * g_idb2[j];
    }
    if (tid < BATCH * NIN) {
        int jj = tid & (NIN - 1);
        g_z1[tid] = x[tid] * g_db1[jj];
    }
}

// ---------------- Q = Gt^T Ht + per-subtile diagonal totals ----------------
// Q[t][w]; 128x128 tile; k = blockIdx.y (t-tile), c = blockIdx.x (w-chunk), NC = ld/128.
// After mainloop, accumulators are parked in smem and 255 threads sum each local diagonal.
template <int R>
__global__ __launch_bounds__(256, 2) void qgemm_kernel(const float* __restrict__ Gt,
                                                       const float* __restrict__ Ht,
                                                       float* __restrict__ Q, int ld,
                                                       float* __restrict__ sub) {
    extern __shared__ float sh[];
    float* sG = sh;             // R x 132
    float* sH = sh + R * 132;   // R x 132   (tile reuses sh after mainloop)
    int k = blockIdx.y, c = blockIdx.x;
    int NC = ld >> 7;
    int t0 = k << 7, w0 = c << 7;
    for (int idx = threadIdx.x; idx < R * 128; idx += 256) {
        int i = idx >> 7, e = idx & 127;
        sG[i * 132 + e] = Gt[i * LSZ + t0 + e];
        sH[i * 132 + e] = Ht[i * LSZ + w0 + e];
    }
    __syncthreads();

    int tx = threadIdx.x & 15, ty = threadIdx.x >> 4;
    float acc[8][8];
#pragma unroll
    for (int u = 0; u < 8; u++)
#pragma unroll
        for (int v = 0; v < 8; v++) acc[u][v] = 0.f;

    for (int i = 0; i < R; i++) {
        float a[8], b[8];
        ((float4*)a)[0] = *(const float4*)&sG[i * 132 + ty * 4];
        ((float4*)a)[1] = *(const float4*)&sG[i * 132 + 64 + ty * 4];
        ((float4*)b)[0] = *(const float4*)&sH[i * 132 + tx * 4];
        ((float4*)b)[1] = *(const float4*)&sH[i * 132 + 64 + tx * 4];
#pragma unroll
        for (int u = 0; u < 8; u++)
#pragma unroll
            for (int v = 0; v < 8; v++) acc[u][v] = fmaf(a[u], b[v], acc[u][v]);
    }
    // global stores
#pragma unroll
    for (int u = 0; u < 8; u++) {
        int t = t0 + (u < 4 ? ty * 4 + u : 64 + ty * 4 + u - 4);
        *(float4*)&Q[(size_t)t * ld + w0 + tx * 4]      = make_float4(acc[u][0], acc[u][1], acc[u][2], acc[u][3]);
        *(float4*)&Q[(size_t)t * ld + w0 + 64 + tx * 4] = make_float4(acc[u][4], acc[u][5], acc[u][6], acc[u][7]);
    }
    __syncthreads();   // everyone done reading sG/sH
    // park tile in smem (reuse sh): 128 x 132
    float* sT = sh;
#pragma unroll
    for (int u = 0; u < 8; u++) {
        int row = (u < 4 ? ty * 4 + u : 64 + ty * 4 + u - 4);
        *(float4*)&sT[row * 132 + tx * 4]      = make_float4(acc[u][0], acc[u][1], acc[u][2], acc[u][3]);
        *(float4*)&sT[row * 132 + 64 + tx * 4] = make_float4(acc[u][4], acc[u][5], acc[u][6], acc[u][7]);
    }
    __syncthreads();
    // per-diagonal totals: local diag dl = tid-127; clamped pointer walk (stride 133)
    int tid = threadIdx.x;
    if (tid < 255) {
        int dl = tid - 127;
        int rlo = dl > 0 ? dl : 0;
        int rhi = dl > 0 ? 128 : 128 + dl;
        const float* p = &sT[rlo * 133 - dl];
        float s = 0.f;
#pragma unroll 4
        for (int r = rlo; r < rhi; r++) {
            s += *p;
            p += 133;
        }
        sub[(k * NC + c) * 256 + tid] = s;
    } else {
        sub[(k * NC + c) * 256 + 255] = 0.f;
    }
}

// ---------------- main GEMM with fused prefix + in-smem diagonal cumsum ----------------
// Ypart[c][b][t] = sum_{w in chunk c} M[t][w] z[b][w], M = diag-cumsum(Q).
// 512 threads (16 warps) for latency hiding; micro 4t x NVb per thread.
// One 128-wide chunk per CTA (blockIdx.y = c); blockIdx.z = batch slice of NB rows.
template <int NB>
__global__ __launch_bounds__(512, 2) void skewgemm_kernel(const float* __restrict__ Q, int ld,
                                                          const float* __restrict__ z, int zld,
                                                          const float* __restrict__ sub,
                                                          float* __restrict__ Ypart, int Tdim) {
    extern __shared__ float sh[];
    float* sM = sh;                 // 128 x 132
    float* sz = sh + 128 * 132;     // NB x 132
    int k = blockIdx.x;
    int c = blockIdx.y;
    int b0 = blockIdx.z * NB;
    int t0 = k << 7;
    int w0 = c << 7;
    int NC = ld >> 7;
    int tx = threadIdx.x & 31;      // t-dim: t = tx + 32u, u<4
    int ty = threadIdx.x >> 5;      // b-dim: 0..15, b = ty + 16v
    int tid = threadIdx.x;
    const int NV = NB / 16;
    float acc[4][NV];
#pragma unroll
    for (int u = 0; u < 4; u++)
#pragma unroll
        for (int v = 0; v < NV; v++) acc[u][v] = 0.f;

    for (int idx = tid; idx < 128 * 32; idx += 512) {
        int row = idx >> 5, c4 = idx & 31;
        float4 m4 = *(const float4*)&Q[(size_t)(t0 + row) * ld + w0 + 4 * c4];
        *(float4*)&sM[row * 132 + 4 * c4] = m4;
    }
    for (int idx = tid; idx < NB * 32; idx += 512) {
        int b = idx >> 5, c4 = idx & 31;
        float4 z4 = *(const float4*)&z[(size_t)(b0 + b) * zld + w0 + 4 * c4];
        *(float4*)&sz[b * 132 + 4 * c4] = z4;
    }
    // ---- prefix for (k,c), overlapped with the tile loads above ----
    // global diag d = 128*(k-c) + (tid-127); earlier subtiles: k2<k any chunk, or k2==k c2<c.
    // chunk candidates per t-tile: q = k2-c2 in {d>>7, (d+127)>>7}.
    float pacc = 0.f;
    if (tid < 255) {
        int d = ((k - c) << 7) + (tid - 127);
        int qlo = d >> 7;
        int qhi = (d + 127) >> 7;
        int jlo = (d - (qlo << 7)) + 127;
        int jhi = (d - (qhi << 7)) + 127;
        for (int k2 = 0; k2 < k; k2++) {
            int c2 = k2 - qlo;
            if (c2 >= 0 && c2 < NC) pacc += sub[(k2 * NC + c2) * 256 + jlo];
            if (qhi != qlo) {
                c2 = k2 - qhi;
                if (c2 >= 0 && c2 < NC) pacc += sub[(k2 * NC + c2) * 256 + jhi];
            }
        }
        int c2 = k - qlo;
        if (c2 >= 0 && c2 < c) pacc += sub[(k * NC + c2) * 256 + jlo];
        if (qhi != qlo) {
            c2 = k - qhi;
            if (c2 >= 0 && c2 < c) pacc += sub[(k * NC + c2) * 256 + jhi];
        }
    }
    __syncthreads();
    // in-smem segmented diagonal cumsum on sM, seeded by pacc (255 threads; stride-133 walk,
    // register-chunked to pipeline the LDS).
    if (tid < 255) {
        int dl = tid - 127;
        int rlo = dl > 0 ? dl : 0;
        int rhi = dl > 0 ? 128 : 128 + dl;
        int len = rhi - rlo;
        float* p = &sM[rlo * 133 - dl];
        float a = pacc;
        int r = 0;
        for (; r + 16 <= len; r += 16) {
            float v[16];
#pragma unroll
            for (int j = 0; j < 16; j++) v[j] = p[j * 133];
#pragma unroll
            for (int j = 0; j < 16; j++) { a += v[j]; p[j * 133] = a; }
            p += 16 * 133;
        }
        for (; r < len; r++) { a += *p; *p = a; p += 133; }
    }
    __syncthreads();
    // ---- FMA mainloop, float4 along ww; 4t x NVb micro ----
    for (int ww = 0; ww < 128; ww += 4) {
        float4 a4[4], z4[NV];
#pragma unroll
        for (int u = 0; u < 4; u++) a4[u] = *(const float4*)&sM[(tx + 32 * u) * 132 + ww];
#pragma unroll
        for (int v = 0; v < NV; v++) z4[v] = *(const float4*)&sz[(ty + 16 * v) * 132 + ww];
#pragma unroll
        for (int u = 0; u < 4; u++)
#pragma unroll
            for (int v = 0; v < NV; v++) {
                acc[u][v] = fmaf(a4[u].x, z4[v].x, acc[u][v]);
                acc[u][v] = fmaf(a4[u].y, z4[v].y, acc[u][v]);
                acc[u][v] = fmaf(a4[u].z, z4[v].z, acc[u][v]);
                acc[u][v] = fmaf(a4[u].w, z4[v].w, acc[u][v]);
            }
    }
#pragma unroll
    for (int u = 0; u < 4; u++) {
        int t = t0 + tx + 32 * u;
#pragma unroll
        for (int v = 0; v < NV; v++) {
            int b = b0 + ty + 16 * v;
            Ypart[((size_t)c * BATCH + b) * Tdim + t] = acc[u][v];
        }
    }
}

// ---------------- epilogue 1: reduce 8 partials, z2 = relu(da1*s + b1) * db2 (full 4096) -------
__global__ void epilogue1_kernel(const float* __restrict__ bias) {
    int i4 = blockIdx.x * 256 + threadIdx.x;
    if (i4 >= BATCH * LSZ / 4) return;
    const float4* Yp = (const float4*)g_Ypart;
    float4 s = Yp[i4];
#pragma unroll
    for (int k = 1; k < 8; k++) {
        float4 p = Yp[(size_t)k * (BATCH * LSZ / 4) + i4];
        s.x += p.x; s.y += p.y; s.z += p.z; s.w += p.w;
    }
    int t = (i4 * 4) & (LSZ - 1);
    float4 dav = *(const float4*)&g_da1[t];
    float4 bv  = *(const float4*)&bias[t];
    float4 db  = *(const float4*)&g_db2[t];
    float4 h;
    h.x = fmaxf(dav.x * s.x + bv.x, 0.f) * db.x;
    h.y = fmaxf(dav.y * s.y + bv.y, 0.f) * db.y;
    h.z = fmaxf(dav.z * s.z + bv.z, 0.f) * db.z;
    h.w = fmaxf(dav.w * s.w + bv.w, 0.f) * db.w;
    ((float4*)g_z2)[i4] = h;
}

// ---------------- fused epilogue2 + logits ----------------
__global__ __launch_bounds__(512) void epilogits_kernel(const float* __restrict__ bias,
                                                        const float* __restrict__ W,
                                                        const float* __restrict__ bl,
                                                        float* __restrict__ out) {
    __shared__ float sh2[FCN];
    int b = blockIdx.x;
    int t = threadIdx.x;            // 512 threads = one t each
    float s = 0.f;
#pragma unroll
    for (int k = 0; k < 32; k++) s += g_Ypart[(size_t)k * BATCH * FCN + b * FCN + t];
    sh2[t] = fmaxf(g_da2[t] * s + bias[t], 0.f);
    __syncthreads();
    int cls = t >> 5;
    int lane = t & 31;
    if (cls < NCLS) {
        float acc = 0.f;
#pragma unroll
        for (int m = 0; m < 16; m++) {
            int j = lane + 32 * m;
            acc = fmaf(sh2[j], W[cls * FCN + j], acc);
        }
#pragma unroll
        for (int off = 16; off; off >>= 1) acc += __shfl_down_sync(0xffffffffu, acc, off);
        if (lane == 0) out[b * NCLS + cls] = acc + bl[cls];
    }
}

// ---------------- launch ----------------
extern "C" void kernel_launch(void* const* d_in, const int* in_sizes, int n_in,
                              void* d_out, int out_size) {
    const float* x    = (const float*)d_in[0];
    const float* G1   = (const float*)d_in[1];
    const float* H1   = (const float*)d_in[2];
    const float* sdA1 = (const float*)d_in[3];
    const float* sdB1 = (const float*)d_in[4];
    const float* b1   = (const float*)d_in[5];
    const float* G2   = (const float*)d_in[6];
    const float* H2   = (const float*)d_in[7];
    const float* sdA2 = (const float*)d_in[8];
    const float* sdB2 = (const float*)d_in[9];
    const float* b2   = (const float*)d_in[10];
    const float* W    = (const float*)d_in[11];
    const float* bl   = (const float*)d_in[12];
    float* out = (float*)d_out;

    const int QSM  = 128 * 132 * 4;               // 67584 (tile park; >= 2*R*132*4 for R<=48)
    const int GSM1 = (128 * 132 + 64 * 132) * 4;  // 101376 (NB=64)
    const int GSM2 = (128 * 132 + 32 * 132) * 4;  // 84480  (NB=32)

    cudaFuncSetAttribute(qgemm_kernel<R1>, cudaFuncAttributeMaxDynamicSharedMemorySize, QSM);
    cudaFuncSetAttribute(qgemm_kernel<R2>, cudaFuncAttributeMaxDynamicSharedMemorySize, QSM);
    cudaFuncSetAttribute(skewgemm_kernel<64>, cudaFuncAttributeMaxDynamicSharedMemorySize, GSM1);
    cudaFuncSetAttribute(skewgemm_kernel<32>, cudaFuncAttributeMaxDynamicSharedMemorySize, GSM2);

    float* Mbuf;  cudaGetSymbolAddress((void**)&Mbuf, g_M);
    float* Sub;   cudaGetSymbolAddress((void**)&Sub, g_sub);
    float* Ypart; cudaGetSymbolAddress((void**)&Ypart, g_Ypart);
    float* z1;    cudaGetSymbolAddress((void**)&z1, g_z1);
    float* z2;    cudaGetSymbolAddress((void**)&z2, g_z2);
    float* Gt1;   cudaGetSymbolAddress((void**)&Gt1, g_Gt1);
    float* Ht1;   cudaGetSymbolAddress((void**)&Ht1, g_Ht1);
    float* Gt2;   cudaGetSymbolAddress((void**)&Gt2, g_Gt2);
    float* Ht2;   cudaGetSymbolAddress((void**)&Ht2, g_Ht2);

    scan_kernel<<<4, 1024>>>(sdA1, sdB1, sdA2, sdB2);
    prep_kernel<<<1024, 256>>>(G1, H1, G2, H2, x);

    // ---- layer 1: strip 4096 x 1024 (input zero-padded beyond 1024); NC=8 ----
    qgemm_kernel<R1><<<dim3(8, 32), 256, QSM>>>(Gt1, Ht1, Mbuf, 1024, Sub);
    skewgemm_kernel<64><<<dim3(32, 8, 1), 512, GSM1>>>(Mbuf, 1024, z1, 1024, Sub, Ypart, LSZ);
    epilogue1_kernel<<<256, 256>>>(b1);

    // ---- layer 2: strip 512 x 4096 (only first 512 outputs used); NC=32 ----
    qgemm_kernel<R2><<<dim3(32, 4), 256, QSM>>>(Gt2, Ht2, Mbuf, 4096, Sub);
    skewgemm_kernel<32><<<dim3(4, 32, 2), 512, GSM2>>>(Mbuf, 4096, z2, 4096, Sub, Ypart, FCN);
    epilogits_kernel<<<64, 512>>>(b2, W, bl, out);
}

// round 13
// speedup vs baseline: 1.0550x; 1.0516x over previous
#include <cuda_runtime.h>

#define LSZ   4096
#define BATCH 64
#define R1    48
#define R2    16
#define NIN   1024
#define FCN   512
#define NCLS  10

// ---------------- scratch (device globals; no allocation allowed) ----------------
__device__ float g_da1[LSZ], g_db1[LSZ], g_da2[LSZ], g_db2[LSZ];
__device__ float g_ida1[LSZ], g_idb1[LSZ], g_ida2[LSZ], g_idb2[LSZ];
__device__ float g_M[(size_t)LSZ*1024];     // 16MB Q strip; layer2 uses 512*4096 = 8MB
__device__ float g_sub[256*256];            // per-subtile diagonal totals (max 32*8 subtiles)
__device__ float g_z2[BATCH*LSZ];           // layer-2 input, 64x4096
__device__ float g_Ypart[8*BATCH*LSZ];      // split-K partials: L1 8 slices, L2 32 slices of 64x512

// ---------------- cumprod scan (shfl-based): d[0]=1, d[j]=prod_{k<j} subd[k]; + reciprocals ----
__global__ void scan_kernel(const float* __restrict__ sA1, const float* __restrict__ sB1,
                            const float* __restrict__ sA2, const float* __restrict__ sB2) {
    const float* src; float* dst; float* inv;
    if      (blockIdx.x == 0) { src = sA1; dst = g_da1; inv = g_ida1; }
    else if (blockIdx.x == 1) { src = sB1; dst = g_db1; inv = g_idb1; }
    else if (blockIdx.x == 2) { src = sA2; dst = g_da2; inv = g_ida2; }
    else                      { src = sB2; dst = g_db2; inv = g_idb2; }

    __shared__ float wtot[32];
    int tid = threadIdx.x;
    int lane = tid & 31, wid = tid >> 5;
    float v[4]; float p = 1.f;
#pragma unroll
    for (int j = 0; j < 4; j++) {
        int idx = tid * 4 + j;
        float s = (idx < LSZ - 1) ? src[idx] : 1.f;
        p *= s; v[j] = p;
    }
    // warp inclusive scan (product) of p
    float ws = p;
#pragma unroll
    for (int off = 1; off < 32; off <<= 1) {
        float o = __shfl_up_sync(0xffffffffu, ws, off);
        if (lane >= off) ws *= o;
    }
    if (lane == 31) wtot[wid] = ws;
    __syncthreads();
    if (wid == 0) {
        float t = wtot[lane];
#pragma unroll
        for (int off = 1; off < 32; off <<= 1) {
            float o = __shfl_up_sync(0xffffffffu, t, off);
            if (lane >= off) t *= o;
        }
        wtot[lane] = t;
    }
    __syncthreads();
    float wpre = (wid == 0) ? 1.f : wtot[wid - 1];
    float wsp = __shfl_up_sync(0xffffffffu, ws, 1);
    float excl = wpre * (lane ? wsp : 1.f);     // exclusive product before this thread
    if (tid == 0) { dst[0] = 1.f; inv[0] = 1.f; }
#pragma unroll
    for (int j = 0; j < 4; j++) {
        int idx = tid * 4 + j;
        if (idx < LSZ - 1) {
            float val = excl * v[j];
            dst[idx + 1] = val;
            inv[idx + 1] = 1.0f / val;
        }
    }
}

// ---------------- Q = (G*ida)^T (H*idb) + per-subtile diagonal totals ----------------
// Scaling folded into the smem load (replaces the old prep pass).
// Q[t][w]; 128x128 tile; k = blockIdx.y (t-tile), c = blockIdx.x (w-chunk), NC = ld/128.
template <int R>
__global__ __launch_bounds__(256, 2) void qgemm_kernel(const float* __restrict__ G,
                                                       const float* __restrict__ H,
                                                       const float* __restrict__ ida,
                                                       const float* __restrict__ idb,
                                                       float* __restrict__ Q, int ld,
                                                       float* __restrict__ sub) {
    extern __shared__ float sh[];
    float* sG = sh;             // R x 132
    float* sH = sh + R * 132;   // R x 132   (tile reuses sh after mainloop)
    int k = blockIdx.y, c = blockIdx.x;
    int NC = ld >> 7;
    int t0 = k << 7, w0 = c << 7;
    {
        int e = threadIdx.x & 127;
        int half = threadIdx.x >> 7;            // 0 or 1
        float sa = ida[t0 + e];
        float sb = idb[w0 + e];
        for (int i = half; i < R; i += 2) {
            sG[i * 132 + e] = G[(size_t)i * LSZ + t0 + e] * sa;
            sH[i * 132 + e] = H[(size_t)i * LSZ + w0 + e] * sb;
        }
    }
    __syncthreads();

    int tx = threadIdx.x & 15, ty = threadIdx.x >> 4;
    float acc[8][8];
#pragma unroll
    for (int u = 0; u < 8; u++)
#pragma unroll
        for (int v = 0; v < 8; v++) acc[u][v] = 0.f;

    for (int i = 0; i < R; i++) {
        float a[8], b[8];
        ((float4*)a)[0] = *(const float4*)&sG[i * 132 + ty * 4];
        ((float4*)a)[1] = *(const float4*)&sG[i * 132 + 64 + ty * 4];
        ((float4*)b)[0] = *(const float4*)&sH[i * 132 + tx * 4];
        ((float4*)b)[1] = *(const float4*)&sH[i * 132 + 64 + tx * 4];
#pragma unroll
        for (int u = 0; u < 8; u++)
#pragma unroll
            for (int v = 0; v < 8; v++) acc[u][v] = fmaf(a[u], b[v], acc[u][v]);
    }
    // global stores
#pragma unroll
    for (int u = 0; u < 8; u++) {
        int t = t0 + (u < 4 ? ty * 4 + u : 64 + ty * 4 + u - 4);
        *(float4*)&Q[(size_t)t * ld + w0 + tx * 4]      = make_float4(acc[u][0], acc[u][1], acc[u][2], acc[u][3]);
        *(float4*)&Q[(size_t)t * ld + w0 + 64 + tx * 4] = make_float4(acc[u][4], acc[u][5], acc[u][6], acc[u][7]);
    }
    __syncthreads();   // everyone done reading sG/sH
    // park tile in smem (reuse sh): 128 x 132
    float* sT = sh;
#pragma unroll
    for (int u = 0; u < 8; u++) {
        int row = (u < 4 ? ty * 4 + u : 64 + ty * 4 + u - 4);
        *(float4*)&sT[row * 132 + tx * 4]      = make_float4(acc[u][0], acc[u][1], acc[u][2], acc[u][3]);
        *(float4*)&sT[row * 132 + 64 + tx * 4] = make_float4(acc[u][4], acc[u][5], acc[u][6], acc[u][7]);
    }
    __syncthreads();
    // per-diagonal totals: local diag dl = tid-127; clamped pointer walk (stride 133)
    int tid = threadIdx.x;
    if (tid < 255) {
        int dl = tid - 127;
        int rlo = dl > 0 ? dl : 0;
        int rhi = dl > 0 ? 128 : 128 + dl;
        const float* p = &sT[rlo * 133 - dl];
        float s = 0.f;
#pragma unroll 4
        for (int r = rlo; r < rhi; r++) {
            s += *p;
            p += 133;
        }
        sub[(k * NC + c) * 256 + tid] = s;
    } else {
        sub[(k * NC + c) * 256 + 255] = 0.f;
    }
}

// ---------------- main GEMM with fused prefix + in-smem diagonal cumsum ----------------
// Ypart[c][b][t] = sum_{w in chunk c} M[t][w] z[b][w], M = diag-cumsum(Q).
// zscale != nullptr folds z[b][w] *= zscale[w] on load (layer 1: z = x, zscale = db1).
// 512 threads (16 warps); micro 4t x NVb; blockIdx.y = chunk c; blockIdx.z = batch slice.
template <int NB>
__global__ __launch_bounds__(512, 2) void skewgemm_kernel(const float* __restrict__ Q, int ld,
                                                          const float* __restrict__ z, int zld,
                                                          const float* __restrict__ zscale,
                                                          const float* __restrict__ sub,
                                                          float* __restrict__ Ypart, int Tdim) {
    extern __shared__ float sh[];
    float* sM = sh;                 // 128 x 132
    float* sz = sh + 128 * 132;     // NB x 132
    int k = blockIdx.x;
    int c = blockIdx.y;
    int b0 = blockIdx.z * NB;
    int t0 = k << 7;
    int w0 = c << 7;
    int NC = ld >> 7;
    int tx = threadIdx.x & 31;      // t-dim: t = tx + 32u, u<4
    int ty = threadIdx.x >> 5;      // b-dim: 0..15, b = ty + 16v
    int tid = threadIdx.x;
    const int NV = NB / 16;
    float acc[4][NV];
#pragma unroll
    for (int u = 0; u < 4; u++)
#pragma unroll
        for (int v = 0; v < NV; v++) acc[u][v] = 0.f;

    for (int idx = tid; idx < 128 * 32; idx += 512) {
        int row = idx >> 5, c4 = idx & 31;
        float4 m4 = *(const float4*)&Q[(size_t)(t0 + row) * ld + w0 + 4 * c4];
        *(float4*)&sM[row * 132 + 4 * c4] = m4;
    }
    if (zscale) {
        for (int idx = tid; idx < NB * 32; idx += 512) {
            int b = idx >> 5, c4 = idx & 31;
            float4 z4 = *(const float4*)&z[(size_t)(b0 + b) * zld + w0 + 4 * c4];
            float4 s4 = *(const float4*)&zscale[w0 + 4 * c4];
            z4.x *= s4.x; z4.y *= s4.y; z4.z *= s4.z; z4.w *= s4.w;
            *(float4*)&sz[b * 132 + 4 * c4] = z4;
        }
    } else {
        for (int idx = tid; idx < NB * 32; idx += 512) {
            int b = idx >> 5, c4 = idx & 31;
            float4 z4 = *(const float4*)&z[(size_t)(b0 + b) * zld + w0 + 4 * c4];
            *(float4*)&sz[b * 132 + 4 * c4] = z4;
        }
    }
    // ---- prefix for (k,c), overlapped with the tile loads above ----
    // global diag d = 128*(k-c) + (tid-127); earlier subtiles: k2<k any chunk, or k2==k c2<c.
    // chunk candidates per t-tile: q = k2-c2 in {d>>7, (d+127)>>7}.
    float pacc = 0.f;
    if (tid < 255) {
        int d = ((k - c) << 7) + (tid - 127);
        int qlo = d >> 7;
        int qhi = (d + 127) >> 7;
        int jlo = (d - (qlo << 7)) + 127;
        int jhi = (d - (qhi << 7)) + 127;
        for (int k2 = 0; k2 < k; k2++) {
            int c2 = k2 - qlo;
            if (c2 >= 0 && c2 < NC) pacc += sub[(k2 * NC + c2) * 256 + jlo];
            if (qhi != qlo) {
                c2 = k2 - qhi;
                if (c2 >= 0 && c2 < NC) pacc += sub[(k2 * NC + c2) * 256 + jhi];
            }
        }
        int c2 = k - qlo;
        if (c2 >= 0 && c2 < c) pacc += sub[(k * NC + c2) * 256 + jlo];
        if (qhi != qlo) {
            c2 = k - qhi;
            if (c2 >= 0 && c2 < c) pacc += sub[(k * NC + c2) * 256 + jhi];
        }
    }
    __syncthreads();
    // in-smem segmented diagonal cumsum on sM, seeded by pacc (255 threads; stride-133 walk,
    // register-chunked to pipeline the LDS).
    if (tid < 255) {
        int dl = tid - 127;
        int rlo = dl > 0 ? dl : 0;
        int rhi = dl > 0 ? 128 : 128 + dl;
        int len = rhi - rlo;
        float* p = &sM[rlo * 133 - dl];
        float a = pacc;
        int r = 0;
        for (; r + 16 <= len; r += 16) {
            float v[16];
#pragma unroll
            for (int j = 0; j < 16; j++) v[j] = p[j * 133];
#pragma unroll
            for (int j = 0; j < 16; j++) { a += v[j]; p[j * 133] = a; }
            p += 16 * 133;
        }
        for (; r < len; r++) { a += *p; *p = a; p += 133; }
    }
    __syncthreads();
    // ---- FMA mainloop, float4 along ww; 4t x NVb micro ----
    for (int ww = 0; ww < 128; ww += 4) {
        float4 a4[4], z4[NV];
#pragma unroll
        for (int u = 0; u < 4; u++) a4[u] = *(const float4*)&sM[(tx + 32 * u) * 132 + ww];
#pragma unroll
        for (int v = 0; v < NV; v++) z4[v] = *(const float4*)&sz[(ty + 16 * v) * 132 + ww];
#pragma unroll
        for (int u = 0; u < 4; u++)
#pragma unroll
            for (int v = 0; v < NV; v++) {
                acc[u][v] = fmaf(a4[u].x, z4[v].x, acc[u][v]);
                acc[u][v] = fmaf(a4[u].y, z4[v].y, acc[u][v]);
                acc[u][v] = fmaf(a4[u].z, z4[v].z, acc[u][v]);
                acc[u][v] = fmaf(a4[u].w, z4[v].w, acc[u][v]);
            }
    }
#pragma unroll
    for (int u = 0; u < 4; u++) {
        int t = t0 + tx + 32 * u;
#pragma unroll
        for (int v = 0; v < NV; v++) {
            int b = b0 + ty + 16 * v;
            Ypart[((size_t)c * BATCH + b) * Tdim + t] = acc[u][v];
        }
    }
}

// ---------------- epilogue 1: reduce 8 partials, z2 = relu(da1*s + b1) * db2 (full 4096) -------
__global__ void epilogue1_kernel(const float* __restrict__ bias) {
    int i4 = blockIdx.x * 256 + threadIdx.x;
    if (i4 >= BATCH * LSZ / 4) return;
    const float4* Yp = (const float4*)g_Ypart;
    float4 s = Yp[i4];
#pragma unroll
    for (int k = 1; k < 8; k++) {
        float4 p = Yp[(size_t)k * (BATCH * LSZ / 4) + i4];
        s.x += p.x; s.y += p.y; s.z += p.z; s.w += p.w;
    }
    int t = (i4 * 4) & (LSZ - 1);
    float4 dav = *(const float4*)&g_da1[t];
    float4 bv  = *(const float4*)&bias[t];
    float4 db  = *(const float4*)&g_db2[t];
    float4 h;
    h.x = fmaxf(dav.x * s.x + bv.x, 0.f) * db.x;
    h.y = fmaxf(dav.y * s.y + bv.y, 0.f) * db.y;
    h.z = fmaxf(dav.z * s.z + bv.z, 0.f) * db.z;
    h.w = fmaxf(dav.w * s.w + bv.w, 0.f) * db.w;
    ((float4*)g_z2)[i4] = h;
}

// ---------------- fused epilogue2 + logits ----------------
__global__ __launch_bounds__(512) void epilogits_kernel(const float* __restrict__ bias,
                                                        const float* __restrict__ W,
                                                        const float* __restrict__ bl,
                                                        float* __restrict__ out) {
    __shared__ float sh2[FCN];
    int b = blockIdx.x;
    int t = threadIdx.x;            // 512 threads = one t each
    float s = 0.f;
#pragma unroll
    for (int k = 0; k < 32; k++) s += g_Ypart[(size_t)k * BATCH * FCN + b * FCN + t];
    sh2[t] = fmaxf(g_da2[t] * s + bias[t], 0.f);
    __syncthreads();
    int cls = t >> 5;
    int lane = t & 31;
    if (cls < NCLS) {
        float acc = 0.f;
#pragma unroll
        for (int m = 0; m < 16; m++) {
            int j = lane + 32 * m;
            acc = fmaf(sh2[j], W[cls * FCN + j], acc);
        }
#pragma unroll
        for (int off = 16; off; off >>= 1) acc += __shfl_down_sync(0xffffffffu, acc, off);
        if (lane == 0) out[b * NCLS + cls] = acc + bl[cls];
    }
}

// ---------------- launch ----------------
extern "C" void kernel_launch(void* const* d_in, const int* in_sizes, int n_in,
                              void* d_out, int out_size) {
    const float* x    = (const float*)d_in[0];
    const float* G1   = (const float*)d_in[1];
    const float* H1   = (const float*)d_in[2];
    const float* sdA1 = (const float*)d_in[3];
    const float* sdB1 = (const float*)d_in[4];
    const float* b1   = (const float*)d_in[5];
    const float* G2   = (const float*)d_in[6];
    const float* H2   = (const float*)d_in[7];
    const float* sdA2 = (const float*)d_in[8];
    const float* sdB2 = (const float*)d_in[9];
    const float* b2   = (const float*)d_in[10];
    const float* W    = (const float*)d_in[11];
    const float* bl   = (const float*)d_in[12];
    float* out = (float*)d_out;

    const int QSM  = 128 * 132 * 4;               // 67584 (tile park; >= 2*R*132*4 for R<=48)
    const int GSM1 = (128 * 132 + 64 * 132) * 4;  // 101376 (NB=64)
    const int GSM2 = (128 * 132 + 32 * 132) * 4;  // 84480  (NB=32)

    cudaFuncSetAttribute(qgemm_kernel<R1>, cudaFuncAttributeMaxDynamicSharedMemorySize, QSM);
    cudaFuncSetAttribute(qgemm_kernel<R2>, cudaFuncAttributeMaxDynamicSharedMemorySize, QSM);
    cudaFuncSetAttribute(skewgemm_kernel<64>, cudaFuncAttributeMaxDynamicSharedMemorySize, GSM1);
    cudaFuncSetAttribute(skewgemm_kernel<32>, cudaFuncAttributeMaxDynamicSharedMemorySize, GSM2);

    float* Mbuf;  cudaGetSymbolAddress((void**)&Mbuf, g_M);
    float* Sub;   cudaGetSymbolAddress((void**)&Sub, g_sub);
    float* Ypart; cudaGetSymbolAddress((void**)&Ypart, g_Ypart);
    float* z2;    cudaGetSymbolAddress((void**)&z2, g_z2);
    float* ida1;  cudaGetSymbolAddress((void**)&ida1, g_ida1);
    float* idb1;  cudaGetSymbolAddress((void**)&idb1, g_idb1);
    float* ida2;  cudaGetSymbolAddress((void**)&ida2, g_ida2);
    float* idb2;  cudaGetSymbolAddress((void**)&idb2, g_idb2);
    float* db1;   cudaGetSymbolAddress((void**)&db1, g_db1);

    scan_kernel<<<4, 1024>>>(sdA1, sdB1, sdA2, sdB2);

    // ---- layer 1: strip 4096 x 1024 (input zero-padded beyond 1024); NC=8 ----
    // G/H scaling and z1 = x*db1 folded into the GEMM loads (no prep pass).
    qgemm_kernel<R1><<<dim3(8, 32), 256, QSM>>>(G1, H1, ida1, idb1, Mbuf, 1024, Sub);
    skewgemm_kernel<64><<<dim3(32, 8, 1), 512, GSM1>>>(Mbuf, 1024, x, 1024, db1, Sub, Ypart, LSZ);
    epilogue1_kernel<<<256, 256>>>(b1);

    // ---- layer 2: strip 512 x 4096 (only first 512 outputs used); NC=32 ----
    qgemm_kernel<R2><<<dim3(32, 4), 256, QSM>>>(G2, H2, ida2, idb2, Mbuf, 4096, Sub);
    skewgemm_kernel<32><<<dim3(4, 32, 2), 512, GSM2>>>(Mbuf, 4096, z2, 4096, nullptr, Sub, Ypart, FCN);
    epilogits_kernel<<<64, 512>>>(b2, W, bl, out);
}

// round 14
// speedup vs baseline: 1.1061x; 1.0485x over previous
#include <cuda_runtime.h>

#define LSZ   4096
#define BATCH 64
#define R1    48
#define R2    16
#define NIN   1024
#define FCN   512
#define NCLS  10

// ---------------- scratch (device globals; no allocation allowed) ----------------
__device__ float g_da1[LSZ], g_db1[LSZ], g_da2[LSZ], g_db2[LSZ];
__device__ float g_ida1[LSZ], g_idb1[LSZ], g_ida2[LSZ], g_idb2[LSZ];
__device__ float g_M[(size_t)LSZ*1024];     // 16MB Q strip; layer2 uses 512*4096 = 8MB
__device__ float g_sub[256*256];            // per-subtile diagonal totals (max 32*8 subtiles)
__device__ float g_Ypart[8*BATCH*LSZ];      // layer-1 split-K partials: 8 slices of 64x4096
__device__ float g_Ypart2[32*BATCH*FCN];    // layer-2 split-K partials: 32 slices of 64x512

// ---------------- cumprod scan (shfl-based): d[0]=1, d[j]=prod_{k<j} subd[k]; + reciprocals ----
__global__ void scan_kernel(const float* __restrict__ sA1, const float* __restrict__ sB1,
                            const float* __restrict__ sA2, const float* __restrict__ sB2) {
    const float* src; float* dst; float* inv;
    if      (blockIdx.x == 0) { src = sA1; dst = g_da1; inv = g_ida1; }
    else if (blockIdx.x == 1) { src = sB1; dst = g_db1; inv = g_idb1; }
    else if (blockIdx.x == 2) { src = sA2; dst = g_da2; inv = g_ida2; }
    else                      { src = sB2; dst = g_db2; inv = g_idb2; }

    __shared__ float wtot[32];
    int tid = threadIdx.x;
    int lane = tid & 31, wid = tid >> 5;
    float v[4]; float p = 1.f;
#pragma unroll
    for (int j = 0; j < 4; j++) {
        int idx = tid * 4 + j;
        float s = (idx < LSZ - 1) ? src[idx] : 1.f;
        p *= s; v[j] = p;
    }
    float ws = p;
#pragma unroll
    for (int off = 1; off < 32; off <<= 1) {
        float o = __shfl_up_sync(0xffffffffu, ws, off);
        if (lane >= off) ws *= o;
    }
    if (lane == 31) wtot[wid] = ws;
    __syncthreads();
    if (wid == 0) {
        float t = wtot[lane];
#pragma unroll
        for (int off = 1; off < 32; off <<= 1) {
            float o = __shfl_up_sync(0xffffffffu, t, off);
            if (lane >= off) t *= o;
        }
        wtot[lane] = t;
    }
    __syncthreads();
    float wpre = (wid == 0) ? 1.f : wtot[wid - 1];
    float wsp = __shfl_up_sync(0xffffffffu, ws, 1);
    float excl = wpre * (lane ? wsp : 1.f);
    if (tid == 0) { dst[0] = 1.f; inv[0] = 1.f; }
#pragma unroll
    for (int j = 0; j < 4; j++) {
        int idx = tid * 4 + j;
        if (idx < LSZ - 1) {
            float val = excl * v[j];
            dst[idx + 1] = val;
            inv[idx + 1] = 1.0f / val;
        }
    }
}

// ---------------- Q = (G*ida)^T (H*idb) + per-subtile diagonal totals ----------------
template <int R>
__global__ __launch_bounds__(256, 2) void qgemm_kernel(const float* __restrict__ G,
                                                       const float* __restrict__ H,
                                                       const float* __restrict__ ida,
                                                       const float* __restrict__ idb,
                                                       float* __restrict__ Q, int ld,
                                                       float* __restrict__ sub) {
    extern __shared__ float sh[];
    float* sG = sh;             // R x 132
    float* sH = sh + R * 132;   // R x 132
    int k = blockIdx.y, c = blockIdx.x;
    int NC = ld >> 7;
    int t0 = k << 7, w0 = c << 7;
    {
        int e = threadIdx.x & 127;
        int half = threadIdx.x >> 7;
        float sa = ida[t0 + e];
        float sb = idb[w0 + e];
        for (int i = half; i < R; i += 2) {
            sG[i * 132 + e] = G[(size_t)i * LSZ + t0 + e] * sa;
            sH[i * 132 + e] = H[(size_t)i * LSZ + w0 + e] * sb;
        }
    }
    __syncthreads();

    int tx = threadIdx.x & 15, ty = threadIdx.x >> 4;
    float acc[8][8];
#pragma unroll
    for (int u = 0; u < 8; u++)
#pragma unroll
        for (int v = 0; v < 8; v++) acc[u][v] = 0.f;

    for (int i = 0; i < R; i++) {
        float a[8], b[8];
        ((float4*)a)[0] = *(const float4*)&sG[i * 132 + ty * 4];
        ((float4*)a)[1] = *(const float4*)&sG[i * 132 + 64 + ty * 4];
        ((float4*)b)[0] = *(const float4*)&sH[i * 132 + tx * 4];
        ((float4*)b)[1] = *(const float4*)&sH[i * 132 + 64 + tx * 4];
#pragma unroll
        for (int u = 0; u < 8; u++)
#pragma unroll
            for (int v = 0; v < 8; v++) acc[u][v] = fmaf(a[u], b[v], acc[u][v]);
    }
#pragma unroll
    for (int u = 0; u < 8; u++) {
        int t = t0 + (u < 4 ? ty * 4 + u : 64 + ty * 4 + u - 4);
        *(float4*)&Q[(size_t)t * ld + w0 + tx * 4]      = make_float4(acc[u][0], acc[u][1], acc[u][2], acc[u][3]);
        *(float4*)&Q[(size_t)t * ld + w0 + 64 + tx * 4] = make_float4(acc[u][4], acc[u][5], acc[u][6], acc[u][7]);
    }
    __syncthreads();
    float* sT = sh;
#pragma unroll
    for (int u = 0; u < 8; u++) {
        int row = (u < 4 ? ty * 4 + u : 64 + ty * 4 + u - 4);
        *(float4*)&sT[row * 132 + tx * 4]      = make_float4(acc[u][0], acc[u][1], acc[u][2], acc[u][3]);
        *(float4*)&sT[row * 132 + 64 + tx * 4] = make_float4(acc[u][4], acc[u][5], acc[u][6], acc[u][7]);
    }
    __syncthreads();
    int tid = threadIdx.x;
    if (tid < 255) {
        int dl = tid - 127;
        int rlo = dl > 0 ? dl : 0;
        int rhi = dl > 0 ? 128 : 128 + dl;
        const float* p = &sT[rlo * 133 - dl];
        float s = 0.f;
#pragma unroll 4
        for (int r = rlo; r < rhi; r++) {
            s += *p;
            p += 133;
        }
        sub[(k * NC + c) * 256 + tid] = s;
    } else {
        sub[(k * NC + c) * 256 + 255] = 0.f;
    }
}

// ---------------- shared device helpers for skew kernels ----------------
__device__ __forceinline__ float diag_prefix(const float* __restrict__ sub,
                                             int k, int c, int NC, int tid) {
    // global diag d = 128*(k-c) + (tid-127); earlier subtiles: k2<k any chunk, or k2==k c2<c.
    float pacc = 0.f;
    int d = ((k - c) << 7) + (tid - 127);
    int qlo = d >> 7;
    int qhi = (d + 127) >> 7;
    int jlo = (d - (qlo << 7)) + 127;
    int jhi = (d - (qhi << 7)) + 127;
    for (int k2 = 0; k2 < k; k2++) {
        int c2 = k2 - qlo;
        if (c2 >= 0 && c2 < NC) pacc += sub[(k2 * NC + c2) * 256 + jlo];
        if (qhi != qlo) {
            c2 = k2 - qhi;
            if (c2 >= 0 && c2 < NC) pacc += sub[(k2 * NC + c2) * 256 + jhi];
        }
    }
    int c2 = k - qlo;
    if (c2 >= 0 && c2 < c) pacc += sub[(k * NC + c2) * 256 + jlo];
    if (qhi != qlo) {
        c2 = k - qhi;
        if (c2 >= 0 && c2 < c) pacc += sub[(k * NC + c2) * 256 + jhi];
    }
    return pacc;
}

__device__ __forceinline__ void diag_cumsum(float* __restrict__ sM, int tid, float pacc) {
    // stride-133 diagonal walk on 128x132 tile, register-chunked
    int dl = tid - 127;
    int rlo = dl > 0 ? dl : 0;
    int rhi = dl > 0 ? 128 : 128 + dl;
    int len = rhi - rlo;
    float* p = &sM[rlo * 133 - dl];
    float a = pacc;
    int r = 0;
    for (; r + 16 <= len; r += 16) {
        float v[16];
#pragma unroll
        for (int j = 0; j < 16; j++) v[j] = p[j * 133];
#pragma unroll
        for (int j = 0; j < 16; j++) { a += v[j]; p[j * 133] = a; }
        p += 16 * 133;
    }
    for (; r < len; r++) { a += *p; *p = a; p += 133; }
}

// ---------------- layer-1 GEMM: Ypart[c][b][t] = sum_{w in chunk c} M1[t][w] (x*db1)[b][w] ----
__global__ __launch_bounds__(512, 2) void skewgemm1_kernel(const float* __restrict__ Q,
                                                           const float* __restrict__ x,
                                                           const float* __restrict__ sub,
                                                           float* __restrict__ Ypart) {
    extern __shared__ float sh[];
    float* sM = sh;                 // 128 x 132
    float* sz = sh + 128 * 132;     // 64 x 132
    const int ld = 1024, NC = 8;
    int k = blockIdx.x;
    int c = blockIdx.y;
    int t0 = k << 7;
    int w0 = c << 7;
    int tx = threadIdx.x & 31;
    int ty = threadIdx.x >> 5;
    int tid = threadIdx.x;
    float acc[4][4];
#pragma unroll
    for (int u = 0; u < 4; u++)
#pragma unroll
        for (int v = 0; v < 4; v++) acc[u][v] = 0.f;

    for (int idx = tid; idx < 128 * 32; idx += 512) {
        int row = idx >> 5, c4 = idx & 31;
        float4 m4 = *(const float4*)&Q[(size_t)(t0 + row) * ld + w0 + 4 * c4];
        *(float4*)&sM[row * 132 + 4 * c4] = m4;
    }
    for (int idx = tid; idx < 64 * 32; idx += 512) {
        int b = idx >> 5, c4 = idx & 31;
        float4 z4 = *(const float4*)&x[(size_t)b * 1024 + w0 + 4 * c4];
        float4 s4 = *(const float4*)&g_db1[w0 + 4 * c4];
        z4.x *= s4.x; z4.y *= s4.y; z4.z *= s4.z; z4.w *= s4.w;
        *(float4*)&sz[b * 132 + 4 * c4] = z4;
    }
    float pacc = (tid < 255) ? diag_prefix(sub, k, c, NC, tid) : 0.f;
    __syncthreads();
    if (tid < 255) diag_cumsum(sM, tid, pacc);
    __syncthreads();
    for (int ww = 0; ww < 128; ww += 4) {
        float4 a4[4], z4[4];
#pragma unroll
        for (int u = 0; u < 4; u++) a4[u] = *(const float4*)&sM[(tx + 32 * u) * 132 + ww];
#pragma unroll
        for (int v = 0; v < 4; v++) z4[v] = *(const float4*)&sz[(ty + 16 * v) * 132 + ww];
#pragma unroll
        for (int u = 0; u < 4; u++)
#pragma unroll
            for (int v = 0; v < 4; v++) {
                acc[u][v] = fmaf(a4[u].x, z4[v].x, acc[u][v]);
                acc[u][v] = fmaf(a4[u].y, z4[v].y, acc[u][v]);
                acc[u][v] = fmaf(a4[u].z, z4[v].z, acc[u][v]);
                acc[u][v] = fmaf(a4[u].w, z4[v].w, acc[u][v]);
            }
    }
#pragma unroll
    for (int u = 0; u < 4; u++) {
        int t = t0 + tx + 32 * u;
#pragma unroll
        for (int v = 0; v < 4; v++) {
            int b = ty + 16 * v;
            Ypart[((size_t)c * BATCH + b) * LSZ + t] = acc[u][v];
        }
    }
}

// ---------------- layer-2 GEMM with FUSED epilogue-1 in the z-load ----------------
// z2[b][w] = relu(da1[w]*sum_k Ypart[k][b][w] + b1[w]) * db2[w], computed inline (bit-identical
// to the old epilogue1: same fixed k=0..7 float4 reduction order).
// Ypart2[c][b][t] = sum_{w in chunk c} M2[t][w] z2[b][w].
__global__ __launch_bounds__(512, 2) void skewgemm2_kernel(const float* __restrict__ Q,
                                                           const float* __restrict__ bias1,
                                                           const float* __restrict__ sub,
                                                           float* __restrict__ Ypart2) {
    extern __shared__ float sh[];
    float* sM = sh;                 // 128 x 132
    float* sz = sh + 128 * 132;     // 32 x 132
    const int ld = 4096, NC = 32;
    int k = blockIdx.x;
    int c = blockIdx.y;
    int b0 = blockIdx.z * 32;
    int t0 = k << 7;
    int w0 = c << 7;
    int tx = threadIdx.x & 31;
    int ty = threadIdx.x >> 5;
    int tid = threadIdx.x;
    float acc[4][2];
#pragma unroll
    for (int u = 0; u < 4; u++)
#pragma unroll
        for (int v = 0; v < 2; v++) acc[u][v] = 0.f;

    for (int idx = tid; idx < 128 * 32; idx += 512) {
        int row = idx >> 5, c4 = idx & 31;
        float4 m4 = *(const float4*)&Q[(size_t)(t0 + row) * ld + w0 + 4 * c4];
        *(float4*)&sM[row * 132 + 4 * c4] = m4;
    }
    // fused z2: reduce 8 layer-1 partials + bias/relu/scales, straight into smem
    {
        const float4* Yp4 = (const float4*)g_Ypart;
        for (int idx = tid; idx < 32 * 32; idx += 512) {
            int b = idx >> 5, c4 = idx & 31;
            int bg = b0 + b;
            int wq = (w0 >> 2) + c4;            // float4 index along w
            float4 s = Yp4[(size_t)bg * 1024 + wq];
#pragma unroll
            for (int kk = 1; kk < 8; kk++) {
                float4 p = Yp4[(size_t)(kk * BATCH + bg) * 1024 + wq];
                s.x += p.x; s.y += p.y; s.z += p.z; s.w += p.w;
            }
            int w = w0 + 4 * c4;
            float4 dav = *(const float4*)&g_da1[w];
            float4 bv  = *(const float4*)&bias1[w];
            float4 db  = *(const float4*)&g_db2[w];
            float4 h;
            h.x = fmaxf(dav.x * s.x + bv.x, 0.f) * db.x;
            h.y = fmaxf(dav.y * s.y + bv.y, 0.f) * db.y;
            h.z = fmaxf(dav.z * s.z + bv.z, 0.f) * db.z;
            h.w = fmaxf(dav.w * s.w + bv.w, 0.f) * db.w;
            *(float4*)&sz[b * 132 + 4 * c4] = h;
        }
    }
    float pacc = (tid < 255) ? diag_prefix(sub, k, c, NC, tid) : 0.f;
    __syncthreads();
    if (tid < 255) diag_cumsum(sM, tid, pacc);
    __syncthreads();
    for (int ww = 0; ww < 128; ww += 4) {
        float4 a4[4], z4[2];
#pragma unroll
        for (int u = 0; u < 4; u++) a4[u] = *(const float4*)&sM[(tx + 32 * u) * 132 + ww];
#pragma unroll
        for (int v = 0; v < 2; v++) z4[v] = *(const float4*)&sz[(ty + 16 * v) * 132 + ww];
#pragma unroll
        for (int u = 0; u < 4; u++)
#pragma unroll
            for (int v = 0; v < 2; v++) {
                acc[u][v] = fmaf(a4[u].x, z4[v].x, acc[u][v]);
                acc[u][v] = fmaf(a4[u].y, z4[v].y, acc[u][v]);
                acc[u][v] = fmaf(a4[u].z, z4[v].z, acc[u][v]);
                acc[u][v] = fmaf(a4[u].w, z4[v].w, acc[u][v]);
            }
    }
#pragma unroll
    for (int u = 0; u < 4; u++) {
        int t = t0 + tx + 32 * u;
#pragma unroll
        for (int v = 0; v < 2; v++) {
            int b = b0 + ty + 16 * v;
            Ypart2[((size_t)c * BATCH + b) * FCN + t] = acc[u][v];
        }
    }
}

// ---------------- fused epilogue2 + logits ----------------
__global__ __launch_bounds__(512) void epilogits_kernel(const float* __restrict__ bias,
                                                        const float* __restrict__ W,
                                                        const float* __restrict__ bl,
                                                        float* __restrict__ out) {
    __shared__ float sh2[FCN];
    int b = blockIdx.x;
    int t = threadIdx.x;
    float s = 0.f;
#pragma unroll
    for (int k = 0; k < 32; k++) s += g_Ypart2[(size_t)k * BATCH * FCN + b * FCN + t];
    sh2[t] = fmaxf(g_da2[t] * s + bias[t], 0.f);
    __syncthreads();
    int cls = t >> 5;
    int lane = t & 31;
    if (cls < NCLS) {
        float acc = 0.f;
#pragma unroll
        for (int m = 0; m < 16; m++) {
            int j = lane + 32 * m;
            acc = fmaf(sh2[j], W[cls * FCN + j], acc);
        }
#pragma unroll
        for (int off = 16; off; off >>= 1) acc += __shfl_down_sync(0xffffffffu, acc, off);
        if (lane == 0) out[b * NCLS + cls] = acc + bl[cls];
    }
}

// ---------------- launch ----------------
extern "C" void kernel_launch(void* const* d_in, const int* in_sizes, int n_in,
                              void* d_out, int out_size) {
    const float* x    = (const float*)d_in[0];
    const float* G1   = (const float*)d_in[1];
    const float* H1   = (const float*)d_in[2];
    const float* sdA1 = (const float*)d_in[3];
    const float* sdB1 = (const float*)d_in[4];
    const float* b1   = (const float*)d_in[5];
    const float* G2   = (const float*)d_in[6];
    const float* H2   = (const float*)d_in[7];
    const float* sdA2 = (const float*)d_in[8];
    const float* sdB2 = (const float*)d_in[9];
    const float* b2   = (const float*)d_in[10];
    const float* W    = (const float*)d_in[11];
    const float* bl   = (const float*)d_in[12];
    float* out = (float*)d_out;

    const int QSM  = 128 * 132 * 4;               // 67584
    const int GSM1 = (128 * 132 + 64 * 132) * 4;  // 101376
    const int GSM2 = (128 * 132 + 32 * 132) * 4;  // 84480

    cudaFuncSetAttribute(qgemm_kernel<R1>, cudaFuncAttributeMaxDynamicSharedMemorySize, QSM);
    cudaFuncSetAttribute(qgemm_kernel<R2>, cudaFuncAttributeMaxDynamicSharedMemorySize, QSM);
    cudaFuncSetAttribute(skewgemm1_kernel, cudaFuncAttributeMaxDynamicSharedMemorySize, GSM1);
    cudaFuncSetAttribute(skewgemm2_kernel, cudaFuncAttributeMaxDynamicSharedMemorySize, GSM2);

    float* Mbuf;  cudaGetSymbolAddress((void**)&Mbuf, g_M);
    float* Sub;   cudaGetSymbolAddress((void**)&Sub, g_sub);
    float* Ypart; cudaGetSymbolAddress((void**)&Ypart, g_Ypart);
    float* Ypart2;cudaGetSymbolAddress((void**)&Ypart2, g_Ypart2);
    float* ida1;  cudaGetSymbolAddress((void**)&ida1, g_ida1);
    float* idb1;  cudaGetSymbolAddress((void**)&idb1, g_idb1);
    float* ida2;  cudaGetSymbolAddress((void**)&ida2, g_ida2);
    float* idb2;  cudaGetSymbolAddress((void**)&idb2, g_idb2);

    scan_kernel<<<4, 1024>>>(sdA1, sdB1, sdA2, sdB2);

    // ---- layer 1: strip 4096 x 1024 (input zero-padded beyond 1024); NC=8 ----
    qgemm_kernel<R1><<<dim3(8, 32), 256, QSM>>>(G1, H1, ida1, idb1, Mbuf, 1024, Sub);
    skewgemm1_kernel<<<dim3(32, 8), 512, GSM1>>>(Mbuf, x, Sub, Ypart);

    // ---- layer 2: strip 512 x 4096 (only first 512 outputs used); NC=32 ----
    // epilogue1 fused into skewgemm2's z-load (reads g_Ypart, L2-resident).
    qgemm_kernel<R2><<<dim3(32, 4), 256, QSM>>>(G2, H2, ida2, idb2, Mbuf, 4096, Sub);
    skewgemm2_kernel<<<dim3(4, 32, 2), 512, GSM2>>>(Mbuf, b1, Sub, Ypart2);
    epilogits_kernel<<<64, 512>>>(b2, W, bl, out);
}

// round 15
// speedup vs baseline: 1.1219x; 1.0142x over previous
#include <cuda_runtime.h>

#define LSZ   4096
#define BATCH 64
#define R1    48
#define R2    16
#define NIN   1024
#define FCN   512
#define NCLS  10

// ---------------- scratch (device globals; no allocation allowed) ----------------
__device__ float g_da1[LSZ], g_db1[LSZ], g_da2[LSZ], g_db2[LSZ];
__device__ float g_ida1[LSZ], g_idb1[LSZ], g_ida2[LSZ], g_idb2[LSZ];
__device__ float g_M[(size_t)LSZ*1024];     // 16MB Q strip; layer2 uses 512*4096 = 8MB
__device__ float g_sub[256*256];            // per-subtile diagonal totals (max 32*8 subtiles)
__device__ float g_Ypart[8*BATCH*LSZ];      // layer-1 split-K partials: 8 slices of 64x4096
__device__ float g_Ypart2[32*BATCH*FCN];    // layer-2 split-K partials: 32 slices of 64x512

// ---------------- cumprod scan (shfl-based): d[0]=1, d[j]=prod_{k<j} subd[k]; + reciprocals ----
__global__ void scan_kernel(const float* __restrict__ sA1, const float* __restrict__ sB1,
                            const float* __restrict__ sA2, const float* __restrict__ sB2) {
    const float* src; float* dst; float* inv;
    if      (blockIdx.x == 0) { src = sA1; dst = g_da1; inv = g_ida1; }
    else if (blockIdx.x == 1) { src = sB1; dst = g_db1; inv = g_idb1; }
    else if (blockIdx.x == 2) { src = sA2; dst = g_da2; inv = g_ida2; }
    else                      { src = sB2; dst = g_db2; inv = g_idb2; }

    __shared__ float wtot[32];
    int tid = threadIdx.x;
    int lane = tid & 31, wid = tid >> 5;
    float v[4]; float p = 1.f;
#pragma unroll
    for (int j = 0; j < 4; j++) {
        int idx = tid * 4 + j;
        float s = (idx < LSZ - 1) ? src[idx] : 1.f;
        p *= s; v[j] = p;
    }
    float ws = p;
#pragma unroll
    for (int off = 1; off < 32; off <<= 1) {
        float o = __shfl_up_sync(0xffffffffu, ws, off);
        if (lane >= off) ws *= o;
    }
    if (lane == 31) wtot[wid] = ws;
    __syncthreads();
    if (wid == 0) {
        float t = wtot[lane];
#pragma unroll
        for (int off = 1; off < 32; off <<= 1) {
            float o = __shfl_up_sync(0xffffffffu, t, off);
            if (lane >= off) t *= o;
        }
        wtot[lane] = t;
    }
    __syncthreads();
    float wpre = (wid == 0) ? 1.f : wtot[wid - 1];
    float wsp = __shfl_up_sync(0xffffffffu, ws, 1);
    float excl = wpre * (lane ? wsp : 1.f);
    if (tid == 0) { dst[0] = 1.f; inv[0] = 1.f; }
#pragma unroll
    for (int j = 0; j < 4; j++) {
        int idx = tid * 4 + j;
        if (idx < LSZ - 1) {
            float val = excl * v[j];
            dst[idx + 1] = val;
            inv[idx + 1] = 1.0f / val;
        }
    }
}

// ---------------- Q = (G*ida)^T (H*idb) + per-subtile diagonal totals ----------------
// 512 threads; micro 8t x 4w; diagonal totals computed by 510 half-diagonal walkers.
template <int R>
__global__ __launch_bounds__(512, 2) void qgemm_kernel(const float* __restrict__ G,
                                                       const float* __restrict__ H,
                                                       const float* __restrict__ ida,
                                                       const float* __restrict__ idb,
                                                       float* __restrict__ Q, int ld,
                                                       float* __restrict__ sub) {
    extern __shared__ float sh[];
    float* sG = sh;                    // R x 132
    float* sH = sh + R * 132;          // R x 132
    float* red = sh + 128 * 132;       // 510 floats (half-diagonal partials)
    int k = blockIdx.y, c = blockIdx.x;
    int NC = ld >> 7;
    int t0 = k << 7, w0 = c << 7;
    int tid = threadIdx.x;
    {
        int e = tid & 127;
        int quarter = tid >> 7;        // 0..3
        float sa = ida[t0 + e];
        float sb = idb[w0 + e];
        for (int i = quarter; i < R; i += 4) {
            sG[i * 132 + e] = G[(size_t)i * LSZ + t0 + e] * sa;
            sH[i * 132 + e] = H[(size_t)i * LSZ + w0 + e] * sb;
        }
    }
    __syncthreads();

    int tx = tid & 31;                 // w: 4 cols at tx*4
    int ty = tid >> 5;                 // t: 8 rows (4+4 split)
    float acc[8][4];
#pragma unroll
    for (int u = 0; u < 8; u++)
#pragma unroll
        for (int v = 0; v < 4; v++) acc[u][v] = 0.f;

    for (int i = 0; i < R; i++) {
        float a[8], b[4];
        ((float4*)a)[0] = *(const float4*)&sG[i * 132 + ty * 4];
        ((float4*)a)[1] = *(const float4*)&sG[i * 132 + 64 + ty * 4];
        ((float4*)b)[0] = *(const float4*)&sH[i * 132 + tx * 4];
#pragma unroll
        for (int u = 0; u < 8; u++)
#pragma unroll
            for (int v = 0; v < 4; v++) acc[u][v] = fmaf(a[u], b[v], acc[u][v]);
    }
#pragma unroll
    for (int u = 0; u < 8; u++) {
        int t = t0 + (u < 4 ? ty * 4 + u : 64 + ty * 4 + u - 4);
        *(float4*)&Q[(size_t)t * ld + w0 + tx * 4] = make_float4(acc[u][0], acc[u][1], acc[u][2], acc[u][3]);
    }
    __syncthreads();   // everyone done reading sG/sH
    // park tile in smem (reuse sh): 128 x 132
    float* sT = sh;
#pragma unroll
    for (int u = 0; u < 8; u++) {
        int row = (u < 4 ? ty * 4 + u : 64 + ty * 4 + u - 4);
        *(float4*)&sT[row * 132 + tx * 4] = make_float4(acc[u][0], acc[u][1], acc[u][2], acc[u][3]);
    }
    __syncthreads();
    // per-diagonal totals: 510 half-diagonal walkers (<=64 steps each), then combine
    if (tid < 510) {
        int j = tid >> 1;              // diagonal index 0..254
        int half = tid & 1;
        int dl = j - 127;
        int rlo = dl > 0 ? dl : 0;
        int rhi = dl > 0 ? 128 : 128 + dl;
        int rm = (rlo + rhi) >> 1;
        int rs = half ? rm : rlo;
        int re = half ? rhi : rm;
        const float* p = &sT[rs * 133 - dl];
        float s = 0.f;
#pragma unroll 4
        for (int r = rs; r < re; r++) {
            s += *p;
            p += 133;
        }
        red[tid] = s;
    }
    __syncthreads();
    if (tid < 255) {
        sub[(k * NC + c) * 256 + tid] = red[2 * tid] + red[2 * tid + 1];
    } else if (tid == 255) {
        sub[(k * NC + c) * 256 + 255] = 0.f;
    }
}

// ---------------- shared device helpers for skew kernels ----------------
__device__ __forceinline__ float diag_prefix(const float* __restrict__ sub,
                                             int k, int c, int NC, int tid) {
    // global diag d = 128*(k-c) + (tid-127); earlier subtiles: k2<k any chunk, or k2==k c2<c.
    float pacc = 0.f;
    int d = ((k - c) << 7) + (tid - 127);
    int qlo = d >> 7;
    int qhi = (d + 127) >> 7;
    int jlo = (d - (qlo << 7)) + 127;
    int jhi = (d - (qhi << 7)) + 127;
    for (int k2 = 0; k2 < k; k2++) {
        int c2 = k2 - qlo;
        if (c2 >= 0 && c2 < NC) pacc += sub[(k2 * NC + c2) * 256 + jlo];
        if (qhi != qlo) {
            c2 = k2 - qhi;
            if (c2 >= 0 && c2 < NC) pacc += sub[(k2 * NC + c2) * 256 + jhi];
        }
    }
    int c2 = k - qlo;
    if (c2 >= 0 && c2 < c) pacc += sub[(k * NC + c2) * 256 + jlo];
    if (qhi != qlo) {
        c2 = k - qhi;
        if (c2 >= 0 && c2 < c) pacc += sub[(k * NC + c2) * 256 + jhi];
    }
    return pacc;
}

__device__ __forceinline__ void diag_cumsum(float* __restrict__ sM, int tid, float pacc) {
    // stride-133 diagonal walk on 128x132 tile, register-chunked
    int dl = tid - 127;
    int rlo = dl > 0 ? dl : 0;
    int rhi = dl > 0 ? 128 : 128 + dl;
    int len = rhi - rlo;
    float* p = &sM[rlo * 133 - dl];
    float a = pacc;
    int r = 0;
    for (; r + 16 <= len; r += 16) {
        float v[16];
#pragma unroll
        for (int j = 0; j < 16; j++) v[j] = p[j * 133];
#pragma unroll
        for (int j = 0; j < 16; j++) { a += v[j]; p[j * 133] = a; }
        p += 16 * 133;
    }
    for (; r < len; r++) { a += *p; *p = a; p += 133; }
}

// ---------------- layer-1 GEMM: Ypart[c][b][t] = sum_{w in chunk c} M1[t][w] (x*db1)[b][w] ----
__global__ __launch_bounds__(512, 2) void skewgemm1_kernel(const float* __restrict__ Q,
                                                           const float* __restrict__ x,
                                                           const float* __restrict__ sub,
                                                           float* __restrict__ Ypart) {
    extern __shared__ float sh[];
    float* sM = sh;                 // 128 x 132
    float* sz = sh + 128 * 132;     // 64 x 132
    const int ld = 1024, NC = 8;
    int k = blockIdx.x;
    int c = blockIdx.y;
    int t0 = k << 7;
    int w0 = c << 7;
    int tx = threadIdx.x & 31;
    int ty = threadIdx.x >> 5;
    int tid = threadIdx.x;
    float acc[4][4];
#pragma unroll
    for (int u = 0; u < 4; u++)
#pragma unroll
        for (int v = 0; v < 4; v++) acc[u][v] = 0.f;

    for (int idx = tid; idx < 128 * 32; idx += 512) {
        int row = idx >> 5, c4 = idx & 31;
        float4 m4 = *(const float4*)&Q[(size_t)(t0 + row) * ld + w0 + 4 * c4];
        *(float4*)&sM[row * 132 + 4 * c4] = m4;
    }
    for (int idx = tid; idx < 64 * 32; idx += 512) {
        int b = idx >> 5, c4 = idx & 31;
        float4 z4 = *(const float4*)&x[(size_t)b * 1024 + w0 + 4 * c4];
        float4 s4 = *(const float4*)&g_db1[w0 + 4 * c4];
        z4.x *= s4.x; z4.y *= s4.y; z4.z *= s4.z; z4.w *= s4.w;
        *(float4*)&sz[b * 132 + 4 * c4] = z4;
    }
    float pacc = (tid < 255) ? diag_prefix(sub, k, c, NC, tid) : 0.f;
    __syncthreads();
    if (tid < 255) diag_cumsum(sM, tid, pacc);
    __syncthreads();
    for (int ww = 0; ww < 128; ww += 4) {
        float4 a4[4], z4[4];
#pragma unroll
        for (int u = 0; u < 4; u++) a4[u] = *(const float4*)&sM[(tx + 32 * u) * 132 + ww];
#pragma unroll
        for (int v = 0; v < 4; v++) z4[v] = *(const float4*)&sz[(ty + 16 * v) * 132 + ww];
#pragma unroll
        for (int u = 0; u < 4; u++)
#pragma unroll
            for (int v = 0; v < 4; v++) {
                acc[u][v] = fmaf(a4[u].x, z4[v].x, acc[u][v]);
                acc[u][v] = fmaf(a4[u].y, z4[v].y, acc[u][v]);
                acc[u][v] = fmaf(a4[u].z, z4[v].z, acc[u][v]);
                acc[u][v] = fmaf(a4[u].w, z4[v].w, acc[u][v]);
            }
    }
#pragma unroll
    for (int u = 0; u < 4; u++) {
        int t = t0 + tx + 32 * u;
#pragma unroll
        for (int v = 0; v < 4; v++) {
            int b = ty + 16 * v;
            Ypart[((size_t)c * BATCH + b) * LSZ + t] = acc[u][v];
        }
    }
}

// ---------------- layer-2 GEMM with FUSED epilogue-1 in the z-load ----------------
__global__ __launch_bounds__(512, 2) void skewgemm2_kernel(const float* __restrict__ Q,
                                                           const float* __restrict__ bias1,
                                                           const float* __restrict__ sub,
                                                           float* __restrict__ Ypart2) {
    extern __shared__ float sh[];
    float* sM = sh;                 // 128 x 132
    float* sz = sh + 128 * 132;     // 32 x 132
    const int ld = 4096, NC = 32;
    int k = blockIdx.x;
    int c = blockIdx.y;
    int b0 = blockIdx.z * 32;
    int t0 = k << 7;
    int w0 = c << 7;
    int tx = threadIdx.x & 31;
    int ty = threadIdx.x >> 5;
    int tid = threadIdx.x;
    float acc[4][2];
#pragma unroll
    for (int u = 0; u < 4; u++)
#pragma unroll
        for (int v = 0; v < 2; v++) acc[u][v] = 0.f;

    for (int idx = tid; idx < 128 * 32; idx += 512) {
        int row = idx >> 5, c4 = idx & 31;
        float4 m4 = *(const float4*)&Q[(size_t)(t0 + row) * ld + w0 + 4 * c4];
        *(float4*)&sM[row * 132 + 4 * c4] = m4;
    }
    // fused z2: reduce 8 layer-1 partials + bias/relu/scales, straight into smem
    {
        const float4* Yp4 = (const float4*)g_Ypart;
        for (int idx = tid; idx < 32 * 32; idx += 512) {
            int b = idx >> 5, c4 = idx & 31;
            int bg = b0 + b;
            int wq = (w0 >> 2) + c4;
            float4 s = Yp4[(size_t)bg * 1024 + wq];
#pragma unroll
            for (int kk = 1; kk < 8; kk++) {
                float4 p = Yp4[(size_t)(kk * BATCH + bg) * 1024 + wq];
                s.x += p.x; s.y += p.y; s.z += p.z; s.w += p.w;
            }
            int w = w0 + 4 * c4;
            float4 dav = *(const float4*)&g_da1[w];
            float4 bv  = *(const float4*)&bias1[w];
            float4 db  = *(const float4*)&g_db2[w];
            float4 h;
            h.x = fmaxf(dav.x * s.x + bv.x, 0.f) * db.x;
            h.y = fmaxf(dav.y * s.y + bv.y, 0.f) * db.y;
            h.z = fmaxf(dav.z * s.z + bv.z, 0.f) * db.z;
            h.w = fmaxf(dav.w * s.w + bv.w, 0.f) * db.w;
            *(float4*)&sz[b * 132 + 4 * c4] = h;
        }
    }
    float pacc = (tid < 255) ? diag_prefix(sub, k, c, NC, tid) : 0.f;
    __syncthreads();
    if (tid < 255) diag_cumsum(sM, tid, pacc);
    __syncthreads();
    for (int ww = 0; ww < 128; ww += 4) {
        float4 a4[4], z4[2];
#pragma unroll
        for (int u = 0; u < 4; u++) a4[u] = *(const float4*)&sM[(tx + 32 * u) * 132 + ww];
#pragma unroll
        for (int v = 0; v < 2; v++) z4[v] = *(const float4*)&sz[(ty + 16 * v) * 132 + ww];
#pragma unroll
        for (int u = 0; u < 4; u++)
#pragma unroll
            for (int v = 0; v < 2; v++) {
                acc[u][v] = fmaf(a4[u].x, z4[v].x, acc[u][v]);
                acc[u][v] = fmaf(a4[u].y, z4[v].y, acc[u][v]);
                acc[u][v] = fmaf(a4[u].z, z4[v].z, acc[u][v]);
                acc[u][v] = fmaf(a4[u].w, z4[v].w, acc[u][v]);
            }
    }
#pragma unroll
    for (int u = 0; u < 4; u++) {
        int t = t0 + tx + 32 * u;
#pragma unroll
        for (int v = 0; v < 2; v++) {
            int b = b0 + ty + 16 * v;
            Ypart2[((size_t)c * BATCH + b) * FCN + t] = acc[u][v];
        }
    }
}

// ---------------- fused epilogue2 + logits ----------------
__global__ __launch_bounds__(512) void epilogits_kernel(const float* __restrict__ bias,
                                                        const float* __restrict__ W,
                                                        const float* __restrict__ bl,
                                                        float* __restrict__ out) {
    __shared__ float sh2[FCN];
    int b = blockIdx.x;
    int t = threadIdx.x;
    float s = 0.f;
#pragma unroll
    for (int k = 0; k < 32; k++) s += g_Ypart2[(size_t)k * BATCH * FCN + b * FCN + t];
    sh2[t] = fmaxf(g_da2[t] * s + bias[t], 0.f);
    __syncthreads();
    int cls = t >> 5;
    int lane = t & 31;
    if (cls < NCLS) {
        float acc = 0.f;
#pragma unroll
        for (int m = 0; m < 16; m++) {
            int j = lane + 32 * m;
            acc = fmaf(sh2[j], W[cls * FCN + j], acc);
        }
#pragma unroll
        for (int off = 16; off; off >>= 1) acc += __shfl_down_sync(0xffffffffu, acc, off);
        if (lane == 0) out[b * NCLS + cls] = acc + bl[cls];
    }
}

// ---------------- launch ----------------
extern "C" void kernel_launch(void* const* d_in, const int* in_sizes, int n_in,
                              void* d_out, int out_size) {
    const float* x    = (const float*)d_in[0];
    const float* G1   = (const float*)d_in[1];
    const float* H1   = (const float*)d_in[2];
    const float* sdA1 = (const float*)d_in[3];
    const float* sdB1 = (const float*)d_in[4];
    const float* b1   = (const float*)d_in[5];
    const float* G2   = (const float*)d_in[6];
    const float* H2   = (const float*)d_in[7];
    const float* sdA2 = (const float*)d_in[8];
    const float* sdB2 = (const float*)d_in[9];
    const float* b2   = (const float*)d_in[10];
    const float* W    = (const float*)d_in[11];
    const float* bl   = (const float*)d_in[12];
    float* out = (float*)d_out;

    const int QSM  = (128 * 132 + 512) * 4;       // 69632 (tile park + half-diag partials)
    const int GSM1 = (128 * 132 + 64 * 132) * 4;  // 101376
    const int GSM2 = (128 * 132 + 32 * 132) * 4;  // 84480

    cudaFuncSetAttribute(qgemm_kernel<R1>, cudaFuncAttributeMaxDynamicSharedMemorySize, QSM);
    cudaFuncSetAttribute(qgemm_kernel<R2>, cudaFuncAttributeMaxDynamicSharedMemorySize, QSM);
    cudaFuncSetAttribute(skewgemm1_kernel, cudaFuncAttributeMaxDynamicSharedMemorySize, GSM1);
    cudaFuncSetAttribute(skewgemm2_kernel, cudaFuncAttributeMaxDynamicSharedMemorySize, GSM2);

    float* Mbuf;  cudaGetSymbolAddress((void**)&Mbuf, g_M);
    float* Sub;   cudaGetSymbolAddress((void**)&Sub, g_sub);
    float* Ypart; cudaGetSymbolAddress((void**)&Ypart, g_Ypart);
    float* Ypart2;cudaGetSymbolAddress((void**)&Ypart2, g_Ypart2);
    float* ida1;  cudaGetSymbolAddress((void**)&ida1, g_ida1);
    float* idb1;  cudaGetSymbolAddress((void**)&idb1, g_idb1);
    float* ida2;  cudaGetSymbolAddress((void**)&ida2, g_ida2);
    float* idb2;  cudaGetSymbolAddress((void**)&idb2, g_idb2);

    scan_kernel<<<4, 1024>>>(sdA1, sdB1, sdA2, sdB2);

    // ---- layer 1: strip 4096 x 1024 (input zero-padded beyond 1024); NC=8 ----
    qgemm_kernel<R1><<<dim3(8, 32), 512, QSM>>>(G1, H1, ida1, idb1, Mbuf, 1024, Sub);
    skewgemm1_kernel<<<dim3(32, 8), 512, GSM1>>>(Mbuf, x, Sub, Ypart);

    // ---- layer 2: strip 512 x 4096 (only first 512 outputs used); NC=32 ----
    qgemm_kernel<R2><<<dim3(32, 4), 512, QSM>>>(G2, H2, ida2, idb2, Mbuf, 4096, Sub);
    skewgemm2_kernel<<<dim3(4, 32, 2), 512, GSM2>>>(Mbuf, b1, Sub, Ypart2);
    epilogits_kernel<<<64, 512>>>(b2, W, bl, out);
}

// round 16
// speedup vs baseline: 1.1357x; 1.0123x over previous
#include <cuda_runtime.h>

#define LSZ   4096
#define BATCH 64
#define R1    48
#define R2    16
#define NIN   1024
#define FCN   512
#define NCLS  10

// ---------------- scratch (device globals; no allocation allowed) ----------------
__device__ float g_da1[LSZ], g_db1[LSZ], g_da2[LSZ], g_db2[LSZ];
__device__ float g_ida1[LSZ], g_idb1[LSZ], g_ida2[LSZ], g_idb2[LSZ];
__device__ float g_M[(size_t)LSZ*1024];     // layer-1 Q strip, 16MB
__device__ float g_M2[(size_t)FCN*LSZ];     // layer-2 Q strip, 8MB (separate: built during skew1)
__device__ float g_sub[256*256];            // layer-1 per-subtile diagonal totals
__device__ float g_sub2[128*256];           // layer-2 per-subtile diagonal totals
__device__ float g_Ypart[8*BATCH*LSZ];      // layer-1 split-K partials: 8 slices of 64x4096
__device__ float g_Ypart2[32*BATCH*FCN];    // layer-2 split-K partials: 32 slices of 64x512

// ---------------- cumprod scan (shfl-based): d[0]=1, d[j]=prod_{k<j} subd[k]; + reciprocals ----
__global__ void scan_kernel(const float* __restrict__ sA1, const float* __restrict__ sB1,
                            const float* __restrict__ sA2, const float* __restrict__ sB2) {
    const float* src; float* dst; float* inv;
    if      (blockIdx.x == 0) { src = sA1; dst = g_da1; inv = g_ida1; }
    else if (blockIdx.x == 1) { src = sB1; dst = g_db1; inv = g_idb1; }
    else if (blockIdx.x == 2) { src = sA2; dst = g_da2; inv = g_ida2; }
    else                      { src = sB2; dst = g_db2; inv = g_idb2; }

    __shared__ float wtot[32];
    int tid = threadIdx.x;
    int lane = tid & 31, wid = tid >> 5;
    float v[4]; float p = 1.f;
#pragma unroll
    for (int j = 0; j < 4; j++) {
        int idx = tid * 4 + j;
        float s = (idx < LSZ - 1) ? src[idx] : 1.f;
        p *= s; v[j] = p;
    }
    float ws = p;
#pragma unroll
    for (int off = 1; off < 32; off <<= 1) {
        float o = __shfl_up_sync(0xffffffffu, ws, off);
        if (lane >= off) ws *= o;
    }
    if (lane == 31) wtot[wid] = ws;
    __syncthreads();
    if (wid == 0) {
        float t = wtot[lane];
#pragma unroll
        for (int off = 1; off < 32; off <<= 1) {
            float o = __shfl_up_sync(0xffffffffu, t, off);
            if (lane >= off) t *= o;
        }
        wtot[lane] = t;
    }
    __syncthreads();
    float wpre = (wid == 0) ? 1.f : wtot[wid - 1];
    float wsp = __shfl_up_sync(0xffffffffu, ws, 1);
    float excl = wpre * (lane ? wsp : 1.f);
    if (tid == 0) { dst[0] = 1.f; inv[0] = 1.f; }
#pragma unroll
    for (int j = 0; j < 4; j++) {
        int idx = tid * 4 + j;
        if (idx < LSZ - 1) {
            float val = excl * v[j];
            dst[idx + 1] = val;
            inv[idx + 1] = 1.0f / val;
        }
    }
}

// ---------------- qgemm body (device): Q = (G*ida)^T (H*idb) + subtile diagonal totals --------
// 512 threads; micro 8t x 4w; diag totals via 510 half-diagonal walkers.
template <int R>
__device__ __forceinline__ void qgemm_body(const float* __restrict__ G,
                                           const float* __restrict__ H,
                                           const float* __restrict__ ida,
                                           const float* __restrict__ idb,
                                           float* __restrict__ Q, int ld,
                                           float* __restrict__ sub,
                                           int k, int c, float* sh) {
    float* sG = sh;                    // R x 132
    float* sH = sh + R * 132;          // R x 132
    float* red = sh + 128 * 132;       // 510 floats
    int NC = ld >> 7;
    int t0 = k << 7, w0 = c << 7;
    int tid = threadIdx.x;
    {
        int e = tid & 127;
        int quarter = tid >> 7;
        float sa = ida[t0 + e];
        float sb = idb[w0 + e];
        for (int i = quarter; i < R; i += 4) {
            sG[i * 132 + e] = G[(size_t)i * LSZ + t0 + e] * sa;
            sH[i * 132 + e] = H[(size_t)i * LSZ + w0 + e] * sb;
        }
    }
    __syncthreads();

    int tx = tid & 31;
    int ty = tid >> 5;
    float acc[8][4];
#pragma unroll
    for (int u = 0; u < 8; u++)
#pragma unroll
        for (int v = 0; v < 4; v++) acc[u][v] = 0.f;

    for (int i = 0; i < R; i++) {
        float a[8], b[4];
        ((float4*)a)[0] = *(const float4*)&sG[i * 132 + ty * 4];
        ((float4*)a)[1] = *(const float4*)&sG[i * 132 + 64 + ty * 4];
        ((float4*)b)[0] = *(const float4*)&sH[i * 132 + tx * 4];
#pragma unroll
        for (int u = 0; u < 8; u++)
#pragma unroll
            for (int v = 0; v < 4; v++) acc[u][v] = fmaf(a[u], b[v], acc[u][v]);
    }
#pragma unroll
    for (int u = 0; u < 8; u++) {
        int t = t0 + (u < 4 ? ty * 4 + u : 64 + ty * 4 + u - 4);
        *(float4*)&Q[(size_t)t * ld + w0 + tx * 4] = make_float4(acc[u][0], acc[u][1], acc[u][2], acc[u][3]);
    }
    __syncthreads();
    float* sT = sh;                    // park: 128 x 132
#pragma unroll
    for (int u = 0; u < 8; u++) {
        int row = (u < 4 ? ty * 4 + u : 64 + ty * 4 + u - 4);
        *(float4*)&sT[row * 132 + tx * 4] = make_float4(acc[u][0], acc[u][1], acc[u][2], acc[u][3]);
    }
    __syncthreads();
    if (tid < 510) {
        int j = tid >> 1;
        int half = tid & 1;
        int dl = j - 127;
        int rlo = dl > 0 ? dl : 0;
        int rhi = dl > 0 ? 128 : 128 + dl;
        int rm = (rlo + rhi) >> 1;
        int rs = half ? rm : rlo;
        int re = half ? rhi : rm;
        const float* p = &sT[rs * 133 - dl];
        float s = 0.f;
#pragma unroll 4
        for (int r = rs; r < re; r++) {
            s += *p;
            p += 133;
        }
        red[tid] = s;
    }
    __syncthreads();
    if (tid < 255) {
        sub[(k * NC + c) * 256 + tid] = red[2 * tid] + red[2 * tid + 1];
    } else if (tid == 255) {
        sub[(k * NC + c) * 256 + 255] = 0.f;
    }
}

template <int R>
__global__ __launch_bounds__(512, 2) void qgemm_kernel(const float* __restrict__ G,
                                                       const float* __restrict__ H,
                                                       const float* __restrict__ ida,
                                                       const float* __restrict__ idb,
                                                       float* __restrict__ Q, int ld,
                                                       float* __restrict__ sub) {
    extern __shared__ float sh[];
    qgemm_body<R>(G, H, ida, idb, Q, ld, sub, blockIdx.y, blockIdx.x, sh);
}

// ---------------- shared device helpers for skew kernels ----------------
__device__ __forceinline__ float diag_prefix(const float* __restrict__ sub,
                                             int k, int c, int NC, int tid) {
    float pacc = 0.f;
    int d = ((k - c) << 7) + (tid - 127);
    int qlo = d >> 7;
    int qhi = (d + 127) >> 7;
    int jlo = (d - (qlo << 7)) + 127;
    int jhi = (d - (qhi << 7)) + 127;
    for (int k2 = 0; k2 < k; k2++) {
        int c2 = k2 - qlo;
        if (c2 >= 0 && c2 < NC) pacc += sub[(k2 * NC + c2) * 256 + jlo];
        if (qhi != qlo) {
            c2 = k2 - qhi;
            if (c2 >= 0 && c2 < NC) pacc += sub[(k2 * NC + c2) * 256 + jhi];
        }
    }
    int c2 = k - qlo;
    if (c2 >= 0 && c2 < c) pacc += sub[(k * NC + c2) * 256 + jlo];
    if (qhi != qlo) {
        c2 = k - qhi;
        if (c2 >= 0 && c2 < c) pacc += sub[(k * NC + c2) * 256 + jhi];
    }
    return pacc;
}

__device__ __forceinline__ void diag_cumsum(float* __restrict__ sM, int tid, float pacc) {
    int dl = tid - 127;
    int rlo = dl > 0 ? dl : 0;
    int rhi = dl > 0 ? 128 : 128 + dl;
    int len = rhi - rlo;
    float* p = &sM[rlo * 133 - dl];
    float a = pacc;
    int r = 0;
    for (; r + 16 <= len; r += 16) {
        float v[16];
#pragma unroll
        for (int j = 0; j < 16; j++) v[j] = p[j * 133];
#pragma unroll
        for (int j = 0; j < 16; j++) { a += v[j]; p[j * 133] = a; }
        p += 16 * 133;
    }
    for (; r < len; r++) { a += *p; *p = a; p += 133; }
}

// ---------------- skew1 body: Ypart[c][b][t] = sum_{w in chunk c} M1[t][w] (x*db1)[b][w] ------
__device__ __forceinline__ void skew1_body(const float* __restrict__ Q,
                                           const float* __restrict__ x,
                                           const float* __restrict__ sub,
                                           float* __restrict__ Ypart,
                                           int k, int c, float* sh) {
    float* sM = sh;                 // 128 x 132
    float* sz = sh + 128 * 132;     // 64 x 132
    const int ld = 1024, NC = 8;
    int t0 = k << 7;
    int w0 = c << 7;
    int tx = threadIdx.x & 31;
    int ty = threadIdx.x >> 5;
    int tid = threadIdx.x;
    float acc[4][4];
#pragma unroll
    for (int u = 0; u < 4; u++)
#pragma unroll
        for (int v = 0; v < 4; v++) acc[u][v] = 0.f;

    for (int idx = tid; idx < 128 * 32; idx += 512) {
        int row = idx >> 5, c4 = idx & 31;
        float4 m4 = *(const float4*)&Q[(size_t)(t0 + row) * ld + w0 + 4 * c4];
        *(float4*)&sM[row * 132 + 4 * c4] = m4;
    }
    for (int idx = tid; idx < 64 * 32; idx += 512) {
        int b = idx >> 5, c4 = idx & 31;
        float4 z4 = *(const float4*)&x[(size_t)b * 1024 + w0 + 4 * c4];
        float4 s4 = *(const float4*)&g_db1[w0 + 4 * c4];
        z4.x *= s4.x; z4.y *= s4.y; z4.z *= s4.z; z4.w *= s4.w;
        *(float4*)&sz[b * 132 + 4 * c4] = z4;
    }
    float pacc = (tid < 255) ? diag_prefix(sub, k, c, NC, tid) : 0.f;
    __syncthreads();
    if (tid < 255) diag_cumsum(sM, tid, pacc);
    __syncthreads();
    for (int ww = 0; ww < 128; ww += 4) {
        float4 a4[4], z4[4];
#pragma unroll
        for (int u = 0; u < 4; u++) a4[u] = *(const float4*)&sM[(tx + 32 * u) * 132 + ww];
#pragma unroll
        for (int v = 0; v < 4; v++) z4[v] = *(const float4*)&sz[(ty + 16 * v) * 132 + ww];
#pragma unroll
        for (int u = 0; u < 4; u++)
#pragma unroll
            for (int v = 0; v < 4; v++) {
                acc[u][v] = fmaf(a4[u].x, z4[v].x, acc[u][v]);
                acc[u][v] = fmaf(a4[u].y, z4[v].y, acc[u][v]);
                acc[u][v] = fmaf(a4[u].z, z4[v].z, acc[u][v]);
                acc[u][v] = fmaf(a4[u].w, z4[v].w, acc[u][v]);
            }
    }
#pragma unroll
    for (int u = 0; u < 4; u++) {
        int t = t0 + tx + 32 * u;
#pragma unroll
        for (int v = 0; v < 4; v++) {
            int b = ty + 16 * v;
            Ypart[((size_t)c * BATCH + b) * LSZ + t] = acc[u][v];
        }
    }
}

// ---------------- FUSED: qgemm2 (CTAs 0..127) + skew1 (CTAs 128..383) ----------------
// qgemm2 is independent of layer 1 -> overlaps with skew1 in one grid. Writes g_M2/g_sub2.
__global__ __launch_bounds__(512, 2) void fused1_kernel(const float* __restrict__ Q1,
                                                        const float* __restrict__ x,
                                                        const float* __restrict__ G2,
                                                        const float* __restrict__ H2,
                                                        float* __restrict__ M2,
                                                        float* __restrict__ sub2) {
    extern __shared__ float sh[];
    int bx = blockIdx.x;
    if (bx < 128) {
        int c = bx & 31, k = bx >> 5;     // layer-2 Q: 4 t-tiles x 32 chunks
        qgemm_body<R2>(G2, H2, g_ida2, g_idb2, M2, 4096, sub2, k, c, sh);
    } else {
        int s = bx - 128;                 // skew1: 32 t-tiles x 8 chunks
        int k = s >> 3, c = s & 7;
        skew1_body(Q1, x, g_sub, g_Ypart, k, c, sh);
    }
}

// ---------------- layer-2 GEMM with FUSED epilogue-1 in the z-load ----------------
__global__ __launch_bounds__(512, 2) void skewgemm2_kernel(const float* __restrict__ Q,
                                                           const float* __restrict__ bias1,
                                                           const float* __restrict__ sub,
                                                           float* __restrict__ Ypart2) {
    extern __shared__ float sh[];
    float* sM = sh;                 // 128 x 132
    float* sz = sh + 128 * 132;     // 32 x 132
    const int ld = 4096, NC = 32;
    int k = blockIdx.x;
    int c = blockIdx.y;
    int b0 = blockIdx.z * 32;
    int t0 = k << 7;
    int w0 = c << 7;
    int tx = threadIdx.x & 31;
    int ty = threadIdx.x >> 5;
    int tid = threadIdx.x;
    float acc[4][2];
#pragma unroll
    for (int u = 0; u < 4; u++)
#pragma unroll
        for (int v = 0; v < 2; v++) acc[u][v] = 0.f;

    for (int idx = tid; idx < 128 * 32; idx += 512) {
        int row = idx >> 5, c4 = idx & 31;
        float4 m4 = *(const float4*)&Q[(size_t)(t0 + row) * ld + w0 + 4 * c4];
        *(float4*)&sM[row * 132 + 4 * c4] = m4;
    }
    // fused z2: reduce 8 layer-1 partials + bias/relu/scales, straight into smem
    {
        const float4* Yp4 = (const float4*)g_Ypart;
        for (int idx = tid; idx < 32 * 32; idx += 512) {
            int b = idx >> 5, c4 = idx & 31;
            int bg = b0 + b;
            int wq = (w0 >> 2) + c4;
            float4 s = Yp4[(size_t)bg * 1024 + wq];
#pragma unroll
            for (int kk = 1; kk < 8; kk++) {
                float4 p = Yp4[(size_t)(kk * BATCH + bg) * 1024 + wq];
                s.x += p.x; s.y += p.y; s.z += p.z; s.w += p.w;
            }
            int w = w0 + 4 * c4;
            float4 dav = *(const float4*)&g_da1[w];
            float4 bv  = *(const float4*)&bias1[w];
            float4 db  = *(const float4*)&g_db2[w];
            float4 h;
            h.x = fmaxf(dav.x * s.x + bv.x, 0.f) * db.x;
            h.y = fmaxf(dav.y * s.y + bv.y, 0.f) * db.y;
            h.z = fmaxf(dav.z * s.z + bv.z, 0.f) * db.z;
            h.w = fmaxf(dav.w * s.w + bv.w, 0.f) * db.w;
            *(float4*)&sz[b * 132 + 4 * c4] = h;
        }
    }
    float pacc = (tid < 255) ? diag_prefix(sub, k, c, NC, tid) : 0.f;
    __syncthreads();
    if (tid < 255) diag_cumsum(sM, tid, pacc);
    __syncthreads();
    for (int ww = 0; ww < 128; ww += 4) {
        float4 a4[4], z4[2];
#pragma unroll
        for (int u = 0; u < 4; u++) a4[u] = *(const float4*)&sM[(tx + 32 * u) * 132 + ww];
#pragma unroll
        for (int v = 0; v < 2; v++) z4[v] = *(const float4*)&sz[(ty + 16 * v) * 132 + ww];
#pragma unroll
        for (int u = 0; u < 4; u++)
#pragma unroll
            for (int v = 0; v < 2; v++) {
                acc[u][v] = fmaf(a4[u].x, z4[v].x, acc[u][v]);
                acc[u][v] = fmaf(a4[u].y, z4[v].y, acc[u][v]);
                acc[u][v] = fmaf(a4[u].z, z4[v].z, acc[u][v]);
                acc[u][v] = fmaf(a4[u].w, z4[v].w, acc[u][v]);
            }
    }
#pragma unroll
    for (int u = 0; u < 4; u++) {
        int t = t0 + tx + 32 * u;
#pragma unroll
        for (int v = 0; v < 2; v++) {
            int b = b0 + ty + 16 * v;
            Ypart2[((size_t)c * BATCH + b) * FCN + t] = acc[u][v];
        }
    }
}

// ---------------- fused epilogue2 + logits ----------------
__global__ __launch_bounds__(512) void epilogits_kernel(const float* __restrict__ bias,
                                                        const float* __restrict__ W,
                                                        const float* __restrict__ bl,
                                                        float* __restrict__ out) {
    __shared__ float sh2[FCN];
    int b = blockIdx.x;
    int t = threadIdx.x;
    float s = 0.f;
#pragma unroll
    for (int k = 0; k < 32; k++) s += g_Ypart2[(size_t)k * BATCH * FCN + b * FCN + t];
    sh2[t] = fmaxf(g_da2[t] * s + bias[t], 0.f);
    __syncthreads();
    int cls = t >> 5;
    int lane = t & 31;
    if (cls < NCLS) {
        float acc = 0.f;
#pragma unroll
        for (int m = 0; m < 16; m++) {
            int j = lane + 32 * m;
            acc = fmaf(sh2[j], W[cls * FCN + j], acc);
        }
#pragma unroll
        for (int off = 16; off; off >>= 1) acc += __shfl_down_sync(0xffffffffu, acc, off);
        if (lane == 0) out[b * NCLS + cls] = acc + bl[cls];
    }
}

// ---------------- launch ----------------
extern "C" void kernel_launch(void* const* d_in, const int* in_sizes, int n_in,
                              void* d_out, int out_size) {
    const float* x    = (const float*)d_in[0];
    const float* G1   = (const float*)d_in[1];
    const float* H1   = (const float*)d_in[2];
    const float* sdA1 = (const float*)d_in[3];
    const float* sdB1 = (const float*)d_in[4];
    const float* b1   = (const float*)d_in[5];
    const float* G2   = (const float*)d_in[6];
    const float* H2   = (const float*)d_in[7];
    const float* sdA2 = (const float*)d_in[8];
    const float* sdB2 = (const float*)d_in[9];
    const float* b2   = (const float*)d_in[10];
    const float* W    = (const float*)d_in[11];
    const float* bl   = (const float*)d_in[12];
    float* out = (float*)d_out;

    const int QSM  = (128 * 132 + 512) * 4;       // 69632
    const int GSM1 = (128 * 132 + 64 * 132) * 4;  // 101376 (also covers qgemm body in fused1)
    const int GSM2 = (128 * 132 + 32 * 132) * 4;  // 84480

    cudaFuncSetAttribute(qgemm_kernel<R1>, cudaFuncAttributeMaxDynamicSharedMemorySize, QSM);
    cudaFuncSetAttribute(fused1_kernel, cudaFuncAttributeMaxDynamicSharedMemorySize, GSM1);
    cudaFuncSetAttribute(skewgemm2_kernel, cudaFuncAttributeMaxDynamicSharedMemorySize, GSM2);

    float* Mbuf;  cudaGetSymbolAddress((void**)&Mbuf, g_M);
    float* M2buf; cudaGetSymbolAddress((void**)&M2buf, g_M2);
    float* Sub;   cudaGetSymbolAddress((void**)&Sub, g_sub);
    float* Sub2;  cudaGetSymbolAddress((void**)&Sub2, g_sub2);
    float* Ypart2;cudaGetSymbolAddress((void**)&Ypart2, g_Ypart2);
    float* ida1;  cudaGetSymbolAddress((void**)&ida1, g_ida1);
    float* idb1;  cudaGetSymbolAddress((void**)&idb1, g_idb1);

    scan_kernel<<<4, 1024>>>(sdA1, sdB1, sdA2, sdB2);

    // ---- layer 1 Q ----
    qgemm_kernel<R1><<<dim3(8, 32), 512, QSM>>>(G1, H1, ida1, idb1, Mbuf, 1024, Sub);

    // ---- fused: skew1 (layer-1 GEMM) + qgemm2 (layer-2 Q, independent of layer 1) ----
    fused1_kernel<<<384, 512, GSM1>>>(Mbuf, x, G2, H2, M2buf, Sub2);

    // ---- layer 2 GEMM (epilogue1 fused in z-load) + logits ----
    skewgemm2_kernel<<<dim3(4, 32, 2), 512, GSM2>>>(M2buf, b1, Sub2, Ypart2);
    epilogits_kernel<<<64, 512>>>(b2, W, bl, out);
}